// round 9
// baseline (speedup 1.0000x reference)
#include <cuda_runtime.h>
#include <cuda_bf16.h>
#include <math.h>

#define NPTS 100000
#define SS 16
#define CC 256
#define GG 16
#define NSROWS (NPTS*SS)

// ---------------- scratch (__device__ globals, per harness rules) ----------------
__device__ float g_Qlin[NPTS*CC];
__device__ float g_Klin[NPTS*CC];
__device__ float g_V[NPTS*CC];
__device__ float g_qg[NPTS*GG];
__device__ float g_kg[NPTS*GG];
__device__ float g_wpre[NPTS*SS*GG];
__device__ float g_Hw[(size_t)NPTS*GG*CC];   // [n][g][c']  1.64 GB
__device__ double g_ds[1100];
// layout: 0 qsum[256], 256 qsq[256], 512 ksum[256], 768 ksq[256],
//         1024 posmom[9] (sx,sy,sz,xx,yy,zz,xy,xz,yz),
//         1040 wsum[16], 1056 wsq[16]
__device__ float g_aq[CC], g_bq[CC], g_ak[CC], g_bk[CC], g_ap[CC], g_bpf[CC];
__device__ float g_Wp2g[CC*GG];  // [c'][g]  grouped-folded Wp2*w_gl
__device__ float g_glb[GG];
__device__ float g_aw[GG], g_bw[GG];

// ---------------- K0: zero accumulators (graph replays must re-zero) ----------------
__global__ void k_zero() {
    int t = blockIdx.x * 256 + threadIdx.x;
    if (t < 1100) g_ds[t] = 0.0;
}

// ---------------- K1: QKV GEMM  Y = feat @ W + b  (64x64x64 tiles, 4x4 micro) ----------------
__global__ void __launch_bounds__(256) k_gemm(
    const float* __restrict__ feat,
    const float* __restrict__ Wq, const float* __restrict__ bq,
    const float* __restrict__ Wk, const float* __restrict__ bk,
    const float* __restrict__ Wv, const float* __restrict__ bv)
{
    __shared__ float As[64][68];
    __shared__ float Bs[64][68];
    int mat = blockIdx.y >> 2;
    int n0  = (blockIdx.y & 3) << 6;
    int m0  = blockIdx.x << 6;
    const float* W    = (mat == 0) ? Wq : ((mat == 1) ? Wk : Wv);
    const float* bias = (mat == 0) ? bq : ((mat == 1) ? bk : bv);
    float* out        = (mat == 0) ? g_Qlin : ((mat == 1) ? g_Klin : g_V);

    int t  = threadIdx.x;
    int tx = t & 15, ty = t >> 4;
    int lr = t >> 4, lc = (t & 15) << 2;

    float acc[4][4];
#pragma unroll
    for (int i = 0; i < 4; i++)
#pragma unroll
        for (int j = 0; j < 4; j++) acc[i][j] = 0.f;

    for (int k0 = 0; k0 < CC; k0 += 64) {
#pragma unroll
        for (int p = 0; p < 4; p++) {
            int row = lr + (p << 4);
            int gm  = m0 + row; if (gm >= NPTS) gm = NPTS - 1;   // clamp OOB loads
            float4 a = *(const float4*)(feat + (size_t)gm * CC + k0 + lc);
            *(float4*)&As[row][lc] = a;
            float4 b = *(const float4*)(W + (size_t)(k0 + row) * CC + n0 + lc);
            *(float4*)&Bs[row][lc] = b;
        }
        __syncthreads();
#pragma unroll
        for (int k = 0; k < 64; k += 4) {
            float a[4][4], b[4][4];
#pragma unroll
            for (int i = 0; i < 4; i++) {
                float4 av = *(const float4*)&As[ty * 4 + i][k];
                a[i][0] = av.x; a[i][1] = av.y; a[i][2] = av.z; a[i][3] = av.w;
            }
#pragma unroll
            for (int kk = 0; kk < 4; kk++) {
                float4 bv4 = *(const float4*)&Bs[k + kk][tx * 4];
                b[kk][0] = bv4.x; b[kk][1] = bv4.y; b[kk][2] = bv4.z; b[kk][3] = bv4.w;
            }
#pragma unroll
            for (int i = 0; i < 4; i++)
#pragma unroll
                for (int kk = 0; kk < 4; kk++)
#pragma unroll
                    for (int j = 0; j < 4; j++)
                        acc[i][j] = fmaf(a[i][kk], b[kk][j], acc[i][j]);
        }
        __syncthreads();
    }
    float4 bb = *(const float4*)(bias + n0 + tx * 4);
#pragma unroll
    for (int i = 0; i < 4; i++) {
        int gm = m0 + ty * 4 + i;
        if (gm < NPTS) {
            float4 o;
            o.x = acc[i][0] + bb.x; o.y = acc[i][1] + bb.y;
            o.z = acc[i][2] + bb.z; o.w = acc[i][3] + bb.w;
            *(float4*)(out + (size_t)gm * CC + n0 + tx * 4) = o;
        }
    }
}

// ---------------- K2: per-channel stats of Qlin, Klin ----------------
__global__ void k_stats_qk() {
    int c = threadIdx.x;
    float s1 = 0, s2 = 0, s3 = 0, s4 = 0;
    for (int n = blockIdx.x; n < NPTS; n += gridDim.x) {
        float x = g_Qlin[(size_t)n * CC + c]; s1 += x; s2 = fmaf(x, x, s2);
        float y = g_Klin[(size_t)n * CC + c]; s3 += y; s4 = fmaf(y, y, s4);
    }
    atomicAdd(&g_ds[c],       (double)s1);
    atomicAdd(&g_ds[256 + c], (double)s2);
    atomicAdd(&g_ds[512 + c], (double)s3);
    atomicAdd(&g_ds[768 + c], (double)s4);
}

// ---------------- K3: pos second moments (closed-form BN stats for P1) ----------------
__global__ void k_posmom(const float* __restrict__ coord, const int* __restrict__ ridx) {
    int i = blockIdx.x * 256 + threadIdx.x;    // over N*S exactly (1.6M = 6250*256)
    int n = i >> 4;
    int r = ridx[i];
    float px = 0, py = 0, pz = 0;
    if (r >= 0) {
        px = coord[r * 3 + 0] - coord[n * 3 + 0];
        py = coord[r * 3 + 1] - coord[n * 3 + 1];
        pz = coord[r * 3 + 2] - coord[n * 3 + 2];
    }
    float v[9] = {px, py, pz, px * px, py * py, pz * pz, px * py, px * pz, py * pz};
    __shared__ float red[8][9];
    int lane = threadIdx.x & 31, w = threadIdx.x >> 5;
#pragma unroll
    for (int j = 0; j < 9; j++)
#pragma unroll
        for (int off = 16; off; off >>= 1)
            v[j] += __shfl_down_sync(0xffffffffu, v[j], off);
    if (lane == 0)
#pragma unroll
        for (int j = 0; j < 9; j++) red[w][j] = v[j];
    __syncthreads();
    if (threadIdx.x < 9) {
        float s = 0;
        for (int w2 = 0; w2 < 8; w2++) s += red[w2][threadIdx.x];
        atomicAdd(&g_ds[1024 + threadIdx.x], (double)s);
    }
}

// ---------------- K4: fold BN params; build Wp2g, glb ----------------
__global__ void k_final1(
    const float* __restrict__ gq, const float* __restrict__ betaq,
    const float* __restrict__ gk, const float* __restrict__ betak,
    const float* __restrict__ Wp1, const float* __restrict__ bp1,
    const float* __restrict__ gp, const float* __restrict__ betap,
    const float* __restrict__ Wp2, const float* __restrict__ bp2,
    const float* __restrict__ w_gl)
{
    int c = threadIdx.x;
    double invN = 1.0 / (double)NPTS;
    {
        double mu = g_ds[c] * invN;
        double var = g_ds[256 + c] * invN - mu * mu;
        float a = (float)((double)gq[c] / sqrt(var + 1e-5));
        g_aq[c] = a; g_bq[c] = betaq[c] - (float)mu * a;
    }
    {
        double mu = g_ds[512 + c] * invN;
        double var = g_ds[768 + c] * invN - mu * mu;
        float a = (float)((double)gk[c] / sqrt(var + 1e-5));
        g_ak[c] = a; g_bk[c] = betak[c] - (float)mu * a;
    }
    {
        double sx = g_ds[1024], sy = g_ds[1025], sz = g_ds[1026];
        double xx = g_ds[1027], yy = g_ds[1028], zz = g_ds[1029];
        double xy = g_ds[1030], xz = g_ds[1031], yz = g_ds[1032];
        double w0 = Wp1[c], w1 = Wp1[256 + c], w2 = Wp1[512 + c], b = bp1[c];
        double invNS = 1.0 / (double)NSROWS;
        double sw = sx * w0 + sy * w1 + sz * w2;
        double mean = sw * invNS + b;
        double ex2 = (w0 * w0 * xx + w1 * w1 * yy + w2 * w2 * zz
                      + 2.0 * (w0 * w1 * xy + w0 * w2 * xz + w1 * w2 * yz)
                      + 2.0 * b * sw) * invNS + b * b;
        double var = ex2 - mean * mean;
        float a = (float)((double)gp[c] / sqrt(var + 1e-5));
        g_ap[c]  = a;
        // h = relu(a * (pos . Wp1[:,c]) + bpf),  bpf folds bp1 + BN shift
        g_bpf[c] = (float)((double)a * b + (double)betap[c] - mean * a);
    }
    // Wp2g[c'][g] = sum_i Wp2[c'][g*16+i] * w_gl[g*16+i]
#pragma unroll
    for (int g = 0; g < GG; g++) {
        float s = 0;
#pragma unroll
        for (int i2 = 0; i2 < 16; i2++)
            s = fmaf(Wp2[(size_t)c * CC + g * 16 + i2], w_gl[g * 16 + i2], s);
        g_Wp2g[c * GG + g] = s;
    }
    if (c < GG) {
        float s = 0;
#pragma unroll
        for (int i2 = 0; i2 < 16; i2++) s = fmaf(bp2[c * 16 + i2], w_gl[c * 16 + i2], s);
        g_glb[c] = s;
    }
}

// ---------------- K5: group-folded q,k vectors  qg[n,g] = sum_i relu(bn(q))*w_gl ----------------
__global__ void __launch_bounds__(256) k_qkgroup(const float* __restrict__ w_gl) {
    int lane = threadIdx.x & 31, warp = threadIdx.x >> 5;
    int n = blockIdx.x * 8 + warp;     // grid = 12500, exact
#pragma unroll
    for (int j = 0; j < 8; j++) {
        int c = lane + 32 * j;
        float wg = w_gl[c];
        float vq = fmaxf(fmaf(g_aq[c], g_Qlin[(size_t)n * CC + c], g_bq[c]), 0.f) * wg;
        float vk = fmaxf(fmaf(g_ak[c], g_Klin[(size_t)n * CC + c], g_bk[c]), 0.f) * wg;
#pragma unroll
        for (int off = 8; off; off >>= 1) {
            vq += __shfl_down_sync(0xffffffffu, vq, off, 16);
            vk += __shfl_down_sync(0xffffffffu, vk, off, 16);
        }
        if (lane == 0)  { g_qg[n * GG + 2 * j]     = vq; g_kg[n * GG + 2 * j]     = vk; }
        if (lane == 16) { g_qg[n * GG + 2 * j + 1] = vq; g_kg[n * GG + 2 * j + 1] = vk; }
    }
}

// ---------------- K6: w_pre logits (pre-group-BN), register-blocked 4 rows x 16 g ----------------
__global__ void __launch_bounds__(256, 1) k_wpre(
    const float* __restrict__ coord, const int* __restrict__ ridx,
    const float* __restrict__ Wp1)
{
    __shared__ float Bs[256][16];      // Wp2g [c'][g]
    __shared__ float P[256][4];        // w0,w1,w2,ap
    __shared__ float Bpf[256];
    __shared__ float glb_s[16];
    int t = threadIdx.x;
    for (int l = t; l < 4096; l += 256) Bs[l >> 4][l & 15] = g_Wp2g[l];
    P[t][0] = Wp1[t]; P[t][1] = Wp1[256 + t]; P[t][2] = Wp1[512 + t]; P[t][3] = g_ap[t];
    Bpf[t] = g_bpf[t];
    if (t < 16) glb_s[t] = g_glb[t];
    __syncthreads();

    int base = blockIdx.x * 1024;
    int rw[4];
    float px[4], py[4], pz[4];
#pragma unroll
    for (int q = 0; q < 4; q++) {
        int row = base + t + q * 256;
        int r = -1;
        float x = 0, y = 0, z = 0;
        if (row < NSROWS) {
            r = ridx[row];
            if (r >= 0) {
                int n = row >> 4;
                x = coord[r * 3 + 0] - coord[n * 3 + 0];
                y = coord[r * 3 + 1] - coord[n * 3 + 1];
                z = coord[r * 3 + 2] - coord[n * 3 + 2];
            }
        }
        rw[q] = r; px[q] = x; py[q] = y; pz[q] = z;
    }

    float acc[4][16];
#pragma unroll
    for (int q = 0; q < 4; q++)
#pragma unroll
        for (int g = 0; g < 16; g++) acc[q][g] = 0.f;

    for (int k = 0; k < 256; k++) {
        float w0 = P[k][0], w1 = P[k][1], w2 = P[k][2], ap = P[k][3], bp = Bpf[k];
        float h[4];
#pragma unroll
        for (int q = 0; q < 4; q++) {
            float pd = fmaf(pz[q], w2, fmaf(py[q], w1, px[q] * w0));
            h[q] = fmaxf(fmaf(ap, pd, bp), 0.f);
        }
#pragma unroll
        for (int g = 0; g < 16; g++) {
            float bg = Bs[k][g];
#pragma unroll
            for (int q = 0; q < 4; q++)
                acc[q][g] = fmaf(h[q], bg, acc[q][g]);
        }
    }

#pragma unroll
    for (int q = 0; q < 4; q++) {
        int row = base + t + q * 256;
        if (row < NSROWS) {
            int n = row >> 4;
            int r = rw[q];
#pragma unroll
            for (int g = 0; g < 16; g++) {
                float kgv = (r >= 0) ? g_kg[(size_t)r * GG + g] : 0.f;
                g_wpre[(size_t)row * GG + g] =
                    kgv - g_qg[(size_t)n * GG + g] + acc[q][g] + glb_s[g];
            }
        }
    }
}

// ---------------- K7: group stats of w_pre ----------------
__global__ void k_wstats() {
    __shared__ float ssum[16], ssq[16];
    int t = threadIdx.x;
    if (t < 16) { ssum[t] = 0.f; ssq[t] = 0.f; }
    __syncthreads();
    int g = t & 15;
    float s1 = 0, s2 = 0;
    for (int row = blockIdx.x * 16 + (t >> 4); row < NSROWS; row += gridDim.x * 16) {
        float x = g_wpre[(size_t)row * GG + g];
        s1 += x; s2 = fmaf(x, x, s2);
    }
    atomicAdd(&ssum[g], s1);
    atomicAdd(&ssq[g], s2);
    __syncthreads();
    if (t < 16) {
        atomicAdd(&g_ds[1040 + t], (double)ssum[t]);
        atomicAdd(&g_ds[1056 + t], (double)ssq[t]);
    }
}

// ---------------- K8: fold group BN ----------------
__global__ void k_final2(const float* __restrict__ g_gl, const float* __restrict__ beta_gl) {
    int g = threadIdx.x;
    if (g < 16) {
        double invNS = 1.0 / (double)NSROWS;
        double mu  = g_ds[1040 + g] * invNS;
        double var = g_ds[1056 + g] * invNS - mu * mu;
        float a = (float)((double)g_gl[g] / sqrt(var + 1e-5));
        g_aw[g] = a; g_bw[g] = beta_gl[g] - (float)mu * a;
    }
}

// ---------------- K9: fused per-point: logits -> softmax -> gathered V + Hw ----------------
__global__ void __launch_bounds__(256) k_pointG(
    const float* __restrict__ coord, const int* __restrict__ ridx,
    const float* __restrict__ Wp1,  const float* __restrict__ bp2,
    const float* __restrict__ Wwe,  const float* __restrict__ bwe,
    float* __restrict__ out)
{
    __shared__ float rl[16][17];
    __shared__ float lg[16][17];
    __shared__ float wsm[16][17];
    __shared__ float wsum[16];
    __shared__ float Wwe_s[16][16];
    __shared__ float bwe_s[16];
    __shared__ float psx[16], psy[16], psz[16];
    __shared__ int   rs[16];

    int n = blockIdx.x, t = threadIdx.x;
    Wwe_s[t >> 4][t & 15] = Wwe[t];
    if (t < 16) {
        bwe_s[t] = bwe[t];
        int r = ridx[n * SS + t];
        rs[t] = r;
        float x = 0, y = 0, z = 0;
        if (r >= 0) {
            x = coord[r * 3 + 0] - coord[n * 3 + 0];
            y = coord[r * 3 + 1] - coord[n * 3 + 1];
            z = coord[r * 3 + 2] - coord[n * 3 + 2];
        }
        psx[t] = x; psy[t] = y; psz[t] = z;
    }
    int s = t >> 4, g = t & 15;
    {
        float x = g_wpre[(size_t)n * 256 + t];
        rl[s][g] = fmaxf(fmaf(g_aw[g], x, g_bw[g]), 0.f);
    }
    __syncthreads();
    {
        float acc = bwe_s[g];
#pragma unroll
        for (int gp2 = 0; gp2 < 16; gp2++)
            acc = fmaf(rl[s][gp2], Wwe_s[gp2][g], acc);
        lg[s][g] = acc;
    }
    __syncthreads();
    if (t < 16) {   // softmax over s for column g = t, then mask
        float m = -1e30f;
#pragma unroll
        for (int ss2 = 0; ss2 < 16; ss2++) m = fmaxf(m, lg[ss2][t]);
        float sum = 0;
        float e[16];
#pragma unroll
        for (int ss2 = 0; ss2 < 16; ss2++) { e[ss2] = expf(lg[ss2][t] - m); sum += e[ss2]; }
        float inv = 1.f / sum;
        float ws = 0;
#pragma unroll
        for (int ss2 = 0; ss2 < 16; ss2++) {
            float w = (rs[ss2] >= 0) ? e[ss2] * inv : 0.f;
            wsm[ss2][t] = w; ws += w;
        }
        wsum[t] = ws;
    }
    __syncthreads();

    int c = t, gc = c >> 4;
    float hw[16];
#pragma unroll
    for (int gg = 0; gg < 16; gg++) hw[gg] = 0.f;
    float out1 = wsum[gc] * bp2[c];
    float w1c = Wp1[c], w2c = Wp1[256 + c], w3c = Wp1[512 + c];
    float apc = g_ap[c], bpc = g_bpf[c];
#pragma unroll
    for (int ss2 = 0; ss2 < 16; ss2++) {
        int r = rs[ss2];
        if (r >= 0) {
            out1 = fmaf(wsm[ss2][gc], g_V[(size_t)r * CC + c], out1);
            float pd = fmaf(psz[ss2], w3c, fmaf(psy[ss2], w2c, psx[ss2] * w1c));
            float h = fmaxf(fmaf(apc, pd, bpc), 0.f);
#pragma unroll
            for (int gg = 0; gg < 16; gg++)
                hw[gg] = fmaf(wsm[ss2][gg], h, hw[gg]);
        }
    }
    out[(size_t)n * CC + c] = out1;
#pragma unroll
    for (int gg = 0; gg < 16; gg++)
        g_Hw[(size_t)n * 4096 + gg * 256 + c] = hw[gg];
}

// ---------------- K10: projection GEMM  out[:, g*16:+16] += Hw[:,g,:] @ Wp2[:, cols] ----------------
__global__ void __launch_bounds__(256) k_projH(
    const float* __restrict__ Wp2, float* __restrict__ out)
{
    __shared__ float Bs2[256][17];
    __shared__ float As[128][33];
    int g = blockIdx.y;
    int n0 = blockIdx.x * 128;
    int t = threadIdx.x;
    for (int l = t; l < 4096; l += 256)
        Bs2[l >> 4][l & 15] = Wp2[(size_t)(l >> 4) * CC + g * 16 + (l & 15)];

    int j = t & 15, rr = t >> 4;
    float acc[8];
#pragma unroll
    for (int q = 0; q < 8; q++) acc[q] = 0.f;

    for (int kc = 0; kc < 8; kc++) {
        int k0 = kc * 32;
        __syncthreads();
        for (int l = t; l < 4096; l += 256) {
            int row = l >> 5, col = l & 31;
            int nn = n0 + row;
            As[row][col] = (nn < NPTS)
                ? g_Hw[(size_t)nn * 4096 + g * 256 + k0 + col] : 0.f;
        }
        __syncthreads();
#pragma unroll
        for (int kk = 0; kk < 32; kk++) {
            float b = Bs2[k0 + kk][j];
#pragma unroll
            for (int q = 0; q < 8; q++)
                acc[q] = fmaf(As[rr + 16 * q][kk], b, acc[q]);
        }
    }
#pragma unroll
    for (int q = 0; q < 8; q++) {
        int nn = n0 + rr + 16 * q;
        if (nn < NPTS) {
            size_t idx = (size_t)nn * CC + g * 16 + j;
            out[idx] += acc[q];
        }
    }
}

// ---------------- launch ----------------
extern "C" void kernel_launch(void* const* d_in, const int* in_sizes, int n_in,
                              void* d_out, int out_size) {
    const float* feat   = (const float*)d_in[0];
    const float* coord  = (const float*)d_in[1];
    const int*   ridx   = (const int*)  d_in[2];
    const float* Wq     = (const float*)d_in[3];
    const float* bq     = (const float*)d_in[4];
    const float* gq     = (const float*)d_in[5];
    const float* betaq  = (const float*)d_in[6];
    const float* Wk     = (const float*)d_in[7];
    const float* bk     = (const float*)d_in[8];
    const float* gk     = (const float*)d_in[9];
    const float* betak  = (const float*)d_in[10];
    const float* Wv     = (const float*)d_in[11];
    const float* bv     = (const float*)d_in[12];
    const float* Wp1    = (const float*)d_in[13];
    const float* bp1    = (const float*)d_in[14];
    const float* gp     = (const float*)d_in[15];
    const float* betap  = (const float*)d_in[16];
    const float* Wp2    = (const float*)d_in[17];
    const float* bp2    = (const float*)d_in[18];
    const float* w_gl   = (const float*)d_in[19];
    const float* g_gl   = (const float*)d_in[20];
    const float* betagl = (const float*)d_in[21];
    const float* Wwe    = (const float*)d_in[22];
    const float* bwe    = (const float*)d_in[23];
    float* out = (float*)d_out;

    k_zero<<<5, 256>>>();
    dim3 gg1((NPTS + 63) / 64, 12);
    k_gemm<<<gg1, 256>>>(feat, Wq, bq, Wk, bk, Wv, bv);
    k_stats_qk<<<256, 256>>>();
    k_posmom<<<NSROWS / 256, 256>>>(coord, ridx);
    k_final1<<<1, 256>>>(gq, betaq, gk, betak, Wp1, bp1, gp, betap, Wp2, bp2, w_gl);
    k_qkgroup<<<NPTS / 8, 256>>>(w_gl);
    k_wpre<<<(NSROWS + 1023) / 1024, 256>>>(coord, ridx, Wp1);
    k_wstats<<<512, 256>>>();
    k_final2<<<1, 32>>>(g_gl, betagl);
    k_pointG<<<NPTS, 256>>>(coord, ridx, Wp1, bp2, Wwe, bwe, out);
    dim3 gg2((NPTS + 127) / 128, 16);
    k_projH<<<gg2, 256>>>(Wp2, out);
}

// round 10
// speedup vs baseline: 1.1177x; 1.1177x over previous
#include <cuda_runtime.h>
#include <cuda_bf16.h>
#include <math.h>
#include <mma.h>

using namespace nvcuda;

#define NPTS 100000
#define SS 16
#define CC 256
#define GG 16
#define NSROWS (NPTS*SS)

// ---------------- scratch (__device__ globals, per harness rules) ----------------
__device__ float g_Qlin[NPTS*CC];
__device__ float g_Klin[NPTS*CC];
__device__ float g_V[NPTS*CC];
__device__ float g_qg[NPTS*GG];
__device__ float g_kg[NPTS*GG];
__device__ float g_wpre[NPTS*SS*GG];
__device__ float g_Hw[(size_t)NPTS*GG*CC];   // [n][g][c']  1.64 GB
__device__ double g_ds[1100];
// layout: 0 qsum[256], 256 qsq[256], 512 ksum[256], 768 ksq[256],
//         1024 posmom[9] (sx,sy,sz,xx,yy,zz,xy,xz,yz),
//         1040 wsum[16], 1056 wsq[16]
__device__ float g_aq[CC], g_bq[CC], g_ak[CC], g_bk[CC], g_ap[CC], g_bpf[CC];
__device__ float g_Wp2g[CC*GG];  // [c'][g]  grouped-folded Wp2*w_gl
__device__ float g_glb[GG];
__device__ float g_aw[GG], g_bw[GG];

// ---------------- K0: zero accumulators (graph replays must re-zero) ----------------
__global__ void k_zero() {
    int t = blockIdx.x * 256 + threadIdx.x;
    if (t < 1100) g_ds[t] = 0.0;
}

// ---------------- K1: QKV GEMM on tensor cores (bf16x3 split, wmma) ----------------
// Y = feat @ W + b,   128(M) x 64(N) block tile, K=256, 8 warps of 32x32.
__device__ __forceinline__ void cvt_store4(__nv_bfloat16* h, __nv_bfloat16* l, float4 v) {
    float xs[4] = {v.x, v.y, v.z, v.w};
    __nv_bfloat16 hh[4], ll[4];
#pragma unroll
    for (int i = 0; i < 4; i++) {
        hh[i] = __float2bfloat16_rn(xs[i]);
        ll[i] = __float2bfloat16_rn(xs[i] - __bfloat162float(hh[i]));
    }
    ((__nv_bfloat162*)h)[0] = __nv_bfloat162(hh[0], hh[1]);
    ((__nv_bfloat162*)h)[1] = __nv_bfloat162(hh[2], hh[3]);
    ((__nv_bfloat162*)l)[0] = __nv_bfloat162(ll[0], ll[1]);
    ((__nv_bfloat162*)l)[1] = __nv_bfloat162(ll[2], ll[3]);
}

__global__ void __launch_bounds__(256) k_gemm_tc(
    const float* __restrict__ feat,
    const float* __restrict__ Wq, const float* __restrict__ bq,
    const float* __restrict__ Wk, const float* __restrict__ bk,
    const float* __restrict__ Wv, const float* __restrict__ bv)
{
    __shared__ __align__(16) char sm[36864];
    __nv_bfloat16 (*Ah)[40] = (__nv_bfloat16(*)[40])(sm);
    __nv_bfloat16 (*Al)[40] = (__nv_bfloat16(*)[40])(sm + 10240);
    __nv_bfloat16 (*Bh)[72] = (__nv_bfloat16(*)[72])(sm + 20480);
    __nv_bfloat16 (*Bl)[72] = (__nv_bfloat16(*)[72])(sm + 25088);

    int mat = blockIdx.y >> 2;
    int n0  = (blockIdx.y & 3) << 6;
    int m0  = blockIdx.x << 7;
    const float* W    = (mat == 0) ? Wq : ((mat == 1) ? Wk : Wv);
    const float* bias = (mat == 0) ? bq : ((mat == 1) ? bk : bv);
    float* out        = (mat == 0) ? g_Qlin : ((mat == 1) ? g_Klin : g_V);

    int t = threadIdx.x;
    int warp = t >> 5, lane = t & 31;
    int wm = warp & 3, wn = warp >> 2;     // 4 M-warps x 2 N-warps

    wmma::fragment<wmma::accumulator, 16, 16, 16, float> acc[2][2];
#pragma unroll
    for (int i = 0; i < 2; i++)
#pragma unroll
        for (int j = 0; j < 2; j++) wmma::fill_fragment(acc[i][j], 0.f);

    for (int k0 = 0; k0 < CC; k0 += 32) {
        // stage A: 128 x 32 floats -> bf16 hi/lo
        {
            int row = t >> 3;
            int col = (t & 7) << 2;
#pragma unroll
            for (int p = 0; p < 4; p++) {
                int rr = row + (p << 5);
                int gm = m0 + rr; if (gm >= NPTS) gm = NPTS - 1;
                float4 v = *(const float4*)(feat + (size_t)gm * CC + k0 + col);
                cvt_store4(&Ah[rr][col], &Al[rr][col], v);
            }
        }
        // stage B: 32 x 64 floats -> bf16 hi/lo
        {
            int row = t >> 4;
            int col = (t & 15) << 2;
#pragma unroll
            for (int p = 0; p < 2; p++) {
                int rr = row + (p << 4);
                float4 v = *(const float4*)(W + (size_t)(k0 + rr) * CC + n0 + col);
                cvt_store4(&Bh[rr][col], &Bl[rr][col], v);
            }
        }
        __syncthreads();
#pragma unroll
        for (int kk = 0; kk < 32; kk += 16) {
            wmma::fragment<wmma::matrix_a, 16, 16, 16, __nv_bfloat16, wmma::row_major> ah[2], al[2];
            wmma::fragment<wmma::matrix_b, 16, 16, 16, __nv_bfloat16, wmma::row_major> bh[2], bl[2];
#pragma unroll
            for (int i = 0; i < 2; i++) {
                wmma::load_matrix_sync(ah[i], &Ah[wm * 32 + i * 16][kk], 40);
                wmma::load_matrix_sync(al[i], &Al[wm * 32 + i * 16][kk], 40);
                wmma::load_matrix_sync(bh[i], &Bh[kk][wn * 32 + i * 16], 72);
                wmma::load_matrix_sync(bl[i], &Bl[kk][wn * 32 + i * 16], 72);
            }
#pragma unroll
            for (int i = 0; i < 2; i++)
#pragma unroll
                for (int j = 0; j < 2; j++) {
                    wmma::mma_sync(acc[i][j], ah[i], bh[j], acc[i][j]);
                    wmma::mma_sync(acc[i][j], ah[i], bl[j], acc[i][j]);
                    wmma::mma_sync(acc[i][j], al[i], bh[j], acc[i][j]);
                }
        }
        __syncthreads();
    }

    // epilogue: per-warp smem staging (reuses tile smem), bias add, guarded stores
    float (*ob)[36] = (float(*)[36])(sm + warp * 4608);
    float bb = bias[n0 + wn * 32 + lane];
#pragma unroll
    for (int i = 0; i < 2; i++) {
        wmma::store_matrix_sync(&ob[i * 16][0],  acc[i][0], 36, wmma::mem_row_major);
        wmma::store_matrix_sync(&ob[i * 16][16], acc[i][1], 36, wmma::mem_row_major);
    }
    __syncwarp();
#pragma unroll
    for (int r = 0; r < 32; r++) {
        int gm = m0 + wm * 32 + r;
        if (gm < NPTS)
            out[(size_t)gm * CC + n0 + wn * 32 + lane] = ob[r][lane] + bb;
    }
}

// ---------------- K2: per-channel stats of Qlin, Klin ----------------
__global__ void k_stats_qk() {
    int c = threadIdx.x;
    float s1 = 0, s2 = 0, s3 = 0, s4 = 0;
    for (int n = blockIdx.x; n < NPTS; n += gridDim.x) {
        float x = g_Qlin[(size_t)n * CC + c]; s1 += x; s2 = fmaf(x, x, s2);
        float y = g_Klin[(size_t)n * CC + c]; s3 += y; s4 = fmaf(y, y, s4);
    }
    atomicAdd(&g_ds[c],       (double)s1);
    atomicAdd(&g_ds[256 + c], (double)s2);
    atomicAdd(&g_ds[512 + c], (double)s3);
    atomicAdd(&g_ds[768 + c], (double)s4);
}

// ---------------- K3: pos second moments (closed-form BN stats for P1) ----------------
__global__ void k_posmom(const float* __restrict__ coord, const int* __restrict__ ridx) {
    int i = blockIdx.x * 256 + threadIdx.x;    // over N*S exactly (1.6M = 6250*256)
    int n = i >> 4;
    int r = ridx[i];
    float px = 0, py = 0, pz = 0;
    if (r >= 0) {
        px = coord[r * 3 + 0] - coord[n * 3 + 0];
        py = coord[r * 3 + 1] - coord[n * 3 + 1];
        pz = coord[r * 3 + 2] - coord[n * 3 + 2];
    }
    float v[9] = {px, py, pz, px * px, py * py, pz * pz, px * py, px * pz, py * pz};
    __shared__ float red[8][9];
    int lane = threadIdx.x & 31, w = threadIdx.x >> 5;
#pragma unroll
    for (int j = 0; j < 9; j++)
#pragma unroll
        for (int off = 16; off; off >>= 1)
            v[j] += __shfl_down_sync(0xffffffffu, v[j], off);
    if (lane == 0)
#pragma unroll
        for (int j = 0; j < 9; j++) red[w][j] = v[j];
    __syncthreads();
    if (threadIdx.x < 9) {
        float s = 0;
        for (int w2 = 0; w2 < 8; w2++) s += red[w2][threadIdx.x];
        atomicAdd(&g_ds[1024 + threadIdx.x], (double)s);
    }
}

// ---------------- K4: fold BN params; build Wp2g, glb ----------------
__global__ void k_final1(
    const float* __restrict__ gq, const float* __restrict__ betaq,
    const float* __restrict__ gk, const float* __restrict__ betak,
    const float* __restrict__ Wp1, const float* __restrict__ bp1,
    const float* __restrict__ gp, const float* __restrict__ betap,
    const float* __restrict__ Wp2, const float* __restrict__ bp2,
    const float* __restrict__ w_gl)
{
    int c = threadIdx.x;
    double invN = 1.0 / (double)NPTS;
    {
        double mu = g_ds[c] * invN;
        double var = g_ds[256 + c] * invN - mu * mu;
        float a = (float)((double)gq[c] / sqrt(var + 1e-5));
        g_aq[c] = a; g_bq[c] = betaq[c] - (float)mu * a;
    }
    {
        double mu = g_ds[512 + c] * invN;
        double var = g_ds[768 + c] * invN - mu * mu;
        float a = (float)((double)gk[c] / sqrt(var + 1e-5));
        g_ak[c] = a; g_bk[c] = betak[c] - (float)mu * a;
    }
    {
        double sx = g_ds[1024], sy = g_ds[1025], sz = g_ds[1026];
        double xx = g_ds[1027], yy = g_ds[1028], zz = g_ds[1029];
        double xy = g_ds[1030], xz = g_ds[1031], yz = g_ds[1032];
        double w0 = Wp1[c], w1 = Wp1[256 + c], w2 = Wp1[512 + c], b = bp1[c];
        double invNS = 1.0 / (double)NSROWS;
        double sw = sx * w0 + sy * w1 + sz * w2;
        double mean = sw * invNS + b;
        double ex2 = (w0 * w0 * xx + w1 * w1 * yy + w2 * w2 * zz
                      + 2.0 * (w0 * w1 * xy + w0 * w2 * xz + w1 * w2 * yz)
                      + 2.0 * b * sw) * invNS + b * b;
        double var = ex2 - mean * mean;
        float a = (float)((double)gp[c] / sqrt(var + 1e-5));
        g_ap[c]  = a;
        g_bpf[c] = (float)((double)a * b + (double)betap[c] - mean * a);
    }
#pragma unroll
    for (int g = 0; g < GG; g++) {
        float s = 0;
#pragma unroll
        for (int i2 = 0; i2 < 16; i2++)
            s = fmaf(Wp2[(size_t)c * CC + g * 16 + i2], w_gl[g * 16 + i2], s);
        g_Wp2g[c * GG + g] = s;
    }
    if (c < GG) {
        float s = 0;
#pragma unroll
        for (int i2 = 0; i2 < 16; i2++) s = fmaf(bp2[c * 16 + i2], w_gl[c * 16 + i2], s);
        g_glb[c] = s;
    }
}

// ---------------- K5: group-folded q,k vectors ----------------
__global__ void __launch_bounds__(256) k_qkgroup(const float* __restrict__ w_gl) {
    int lane = threadIdx.x & 31, warp = threadIdx.x >> 5;
    int n = blockIdx.x * 8 + warp;     // grid = 12500, exact
#pragma unroll
    for (int j = 0; j < 8; j++) {
        int c = lane + 32 * j;
        float wg = w_gl[c];
        float vq = fmaxf(fmaf(g_aq[c], g_Qlin[(size_t)n * CC + c], g_bq[c]), 0.f) * wg;
        float vk = fmaxf(fmaf(g_ak[c], g_Klin[(size_t)n * CC + c], g_bk[c]), 0.f) * wg;
#pragma unroll
        for (int off = 8; off; off >>= 1) {
            vq += __shfl_down_sync(0xffffffffu, vq, off, 16);
            vk += __shfl_down_sync(0xffffffffu, vk, off, 16);
        }
        if (lane == 0)  { g_qg[n * GG + 2 * j]     = vq; g_kg[n * GG + 2 * j]     = vk; }
        if (lane == 16) { g_qg[n * GG + 2 * j + 1] = vq; g_kg[n * GG + 2 * j + 1] = vk; }
    }
}

// ---------------- K6: w_pre logits (pre-group-BN) ----------------
__global__ void __launch_bounds__(256, 1) k_wpre(
    const float* __restrict__ coord, const int* __restrict__ ridx,
    const float* __restrict__ Wp1)
{
    __shared__ float Bs[256][16];
    __shared__ float P[256][4];
    __shared__ float Bpf[256];
    __shared__ float glb_s[16];
    int t = threadIdx.x;
    for (int l = t; l < 4096; l += 256) Bs[l >> 4][l & 15] = g_Wp2g[l];
    P[t][0] = Wp1[t]; P[t][1] = Wp1[256 + t]; P[t][2] = Wp1[512 + t]; P[t][3] = g_ap[t];
    Bpf[t] = g_bpf[t];
    if (t < 16) glb_s[t] = g_glb[t];
    __syncthreads();

    int base = blockIdx.x * 1024;
    int rw[4];
    float px[4], py[4], pz[4];
#pragma unroll
    for (int q = 0; q < 4; q++) {
        int row = base + t + q * 256;
        int r = -1;
        float x = 0, y = 0, z = 0;
        if (row < NSROWS) {
            r = ridx[row];
            if (r >= 0) {
                int n = row >> 4;
                x = coord[r * 3 + 0] - coord[n * 3 + 0];
                y = coord[r * 3 + 1] - coord[n * 3 + 1];
                z = coord[r * 3 + 2] - coord[n * 3 + 2];
            }
        }
        rw[q] = r; px[q] = x; py[q] = y; pz[q] = z;
    }

    float acc[4][16];
#pragma unroll
    for (int q = 0; q < 4; q++)
#pragma unroll
        for (int g = 0; g < 16; g++) acc[q][g] = 0.f;

    for (int k = 0; k < 256; k++) {
        float w0 = P[k][0], w1 = P[k][1], w2 = P[k][2], ap = P[k][3], bp = Bpf[k];
        float h[4];
#pragma unroll
        for (int q = 0; q < 4; q++) {
            float pd = fmaf(pz[q], w2, fmaf(py[q], w1, px[q] * w0));
            h[q] = fmaxf(fmaf(ap, pd, bp), 0.f);
        }
#pragma unroll
        for (int g = 0; g < 16; g++) {
            float bg = Bs[k][g];
#pragma unroll
            for (int q = 0; q < 4; q++)
                acc[q][g] = fmaf(h[q], bg, acc[q][g]);
        }
    }

#pragma unroll
    for (int q = 0; q < 4; q++) {
        int row = base + t + q * 256;
        if (row < NSROWS) {
            int n = row >> 4;
            int r = rw[q];
#pragma unroll
            for (int g = 0; g < 16; g++) {
                float kgv = (r >= 0) ? g_kg[(size_t)r * GG + g] : 0.f;
                g_wpre[(size_t)row * GG + g] =
                    kgv - g_qg[(size_t)n * GG + g] + acc[q][g] + glb_s[g];
            }
        }
    }
}

// ---------------- K7: group stats of w_pre ----------------
__global__ void k_wstats() {
    __shared__ float ssum[16], ssq[16];
    int t = threadIdx.x;
    if (t < 16) { ssum[t] = 0.f; ssq[t] = 0.f; }
    __syncthreads();
    int g = t & 15;
    float s1 = 0, s2 = 0;
    for (int row = blockIdx.x * 16 + (t >> 4); row < NSROWS; row += gridDim.x * 16) {
        float x = g_wpre[(size_t)row * GG + g];
        s1 += x; s2 = fmaf(x, x, s2);
    }
    atomicAdd(&ssum[g], s1);
    atomicAdd(&ssq[g], s2);
    __syncthreads();
    if (t < 16) {
        atomicAdd(&g_ds[1040 + t], (double)ssum[t]);
        atomicAdd(&g_ds[1056 + t], (double)ssq[t]);
    }
}

// ---------------- K8: fold group BN ----------------
__global__ void k_final2(const float* __restrict__ g_gl, const float* __restrict__ beta_gl) {
    int g = threadIdx.x;
    if (g < 16) {
        double invNS = 1.0 / (double)NSROWS;
        double mu  = g_ds[1040 + g] * invNS;
        double var = g_ds[1056 + g] * invNS - mu * mu;
        float a = (float)((double)g_gl[g] / sqrt(var + 1e-5));
        g_aw[g] = a; g_bw[g] = beta_gl[g] - (float)mu * a;
    }
}

// ---------------- K9: fused per-point: logits -> softmax -> gathered V + Hw ----------------
__global__ void __launch_bounds__(256) k_pointG(
    const float* __restrict__ coord, const int* __restrict__ ridx,
    const float* __restrict__ Wp1,  const float* __restrict__ bp2,
    const float* __restrict__ Wwe,  const float* __restrict__ bwe,
    float* __restrict__ out)
{
    __shared__ float rl[16][17];
    __shared__ float lg[16][17];
    __shared__ float wsm[16][17];
    __shared__ float wsum[16];
    __shared__ float Wwe_s[16][16];
    __shared__ float bwe_s[16];
    __shared__ float psx[16], psy[16], psz[16];
    __shared__ int   rs[16];

    int n = blockIdx.x, t = threadIdx.x;
    Wwe_s[t >> 4][t & 15] = Wwe[t];
    if (t < 16) {
        bwe_s[t] = bwe[t];
        int r = ridx[n * SS + t];
        rs[t] = r;
        float x = 0, y = 0, z = 0;
        if (r >= 0) {
            x = coord[r * 3 + 0] - coord[n * 3 + 0];
            y = coord[r * 3 + 1] - coord[n * 3 + 1];
            z = coord[r * 3 + 2] - coord[n * 3 + 2];
        }
        psx[t] = x; psy[t] = y; psz[t] = z;
    }
    int s = t >> 4, g = t & 15;
    {
        float x = g_wpre[(size_t)n * 256 + t];
        rl[s][g] = fmaxf(fmaf(g_aw[g], x, g_bw[g]), 0.f);
    }
    __syncthreads();
    {
        float acc = bwe_s[g];
#pragma unroll
        for (int gp2 = 0; gp2 < 16; gp2++)
            acc = fmaf(rl[s][gp2], Wwe_s[gp2][g], acc);
        lg[s][g] = acc;
    }
    __syncthreads();
    if (t < 16) {
        float m = -1e30f;
#pragma unroll
        for (int ss2 = 0; ss2 < 16; ss2++) m = fmaxf(m, lg[ss2][t]);
        float sum = 0;
        float e[16];
#pragma unroll
        for (int ss2 = 0; ss2 < 16; ss2++) { e[ss2] = expf(lg[ss2][t] - m); sum += e[ss2]; }
        float inv = 1.f / sum;
        float ws = 0;
#pragma unroll
        for (int ss2 = 0; ss2 < 16; ss2++) {
            float w = (rs[ss2] >= 0) ? e[ss2] * inv : 0.f;
            wsm[ss2][t] = w; ws += w;
        }
        wsum[t] = ws;
    }
    __syncthreads();

    int c = t, gc = c >> 4;
    float hw[16];
#pragma unroll
    for (int gg = 0; gg < 16; gg++) hw[gg] = 0.f;
    float out1 = wsum[gc] * bp2[c];
    float w1c = Wp1[c], w2c = Wp1[256 + c], w3c = Wp1[512 + c];
    float apc = g_ap[c], bpc = g_bpf[c];
#pragma unroll
    for (int ss2 = 0; ss2 < 16; ss2++) {
        int r = rs[ss2];
        if (r >= 0) {
            out1 = fmaf(wsm[ss2][gc], g_V[(size_t)r * CC + c], out1);
            float pd = fmaf(psz[ss2], w3c, fmaf(psy[ss2], w2c, psx[ss2] * w1c));
            float h = fmaxf(fmaf(apc, pd, bpc), 0.f);
#pragma unroll
            for (int gg = 0; gg < 16; gg++)
                hw[gg] = fmaf(wsm[ss2][gg], h, hw[gg]);
        }
    }
    out[(size_t)n * CC + c] = out1;
#pragma unroll
    for (int gg = 0; gg < 16; gg++)
        g_Hw[(size_t)n * 4096 + gg * 256 + c] = hw[gg];
}

// ---------------- K10: projection GEMM  out[:, g*16:+16] += Hw[:,g,:] @ Wp2[:, cols] ----------------
__global__ void __launch_bounds__(256) k_projH(
    const float* __restrict__ Wp2, float* __restrict__ out)
{
    __shared__ float Bs2[256][17];
    __shared__ float As[128][33];
    int g = blockIdx.y;
    int n0 = blockIdx.x * 128;
    int t = threadIdx.x;
    for (int l = t; l < 4096; l += 256)
        Bs2[l >> 4][l & 15] = Wp2[(size_t)(l >> 4) * CC + g * 16 + (l & 15)];

    int j = t & 15, rr = t >> 4;
    float acc[8];
#pragma unroll
    for (int q = 0; q < 8; q++) acc[q] = 0.f;

    for (int kc = 0; kc < 8; kc++) {
        int k0 = kc * 32;
        __syncthreads();
        for (int l = t; l < 4096; l += 256) {
            int row = l >> 5, col = l & 31;
            int nn = n0 + row;
            As[row][col] = (nn < NPTS)
                ? g_Hw[(size_t)nn * 4096 + g * 256 + k0 + col] : 0.f;
        }
        __syncthreads();
#pragma unroll
        for (int kk = 0; kk < 32; kk++) {
            float b = Bs2[k0 + kk][j];
#pragma unroll
            for (int q = 0; q < 8; q++)
                acc[q] = fmaf(As[rr + 16 * q][kk], b, acc[q]);
        }
    }
#pragma unroll
    for (int q = 0; q < 8; q++) {
        int nn = n0 + rr + 16 * q;
        if (nn < NPTS) {
            size_t idx = (size_t)nn * CC + g * 16 + j;
            out[idx] += acc[q];
        }
    }
}

// ---------------- launch ----------------
extern "C" void kernel_launch(void* const* d_in, const int* in_sizes, int n_in,
                              void* d_out, int out_size) {
    const float* feat   = (const float*)d_in[0];
    const float* coord  = (const float*)d_in[1];
    const int*   ridx   = (const int*)  d_in[2];
    const float* Wq     = (const float*)d_in[3];
    const float* bq     = (const float*)d_in[4];
    const float* gq     = (const float*)d_in[5];
    const float* betaq  = (const float*)d_in[6];
    const float* Wk     = (const float*)d_in[7];
    const float* bk     = (const float*)d_in[8];
    const float* gk     = (const float*)d_in[9];
    const float* betak  = (const float*)d_in[10];
    const float* Wv     = (const float*)d_in[11];
    const float* bv     = (const float*)d_in[12];
    const float* Wp1    = (const float*)d_in[13];
    const float* bp1    = (const float*)d_in[14];
    const float* gp     = (const float*)d_in[15];
    const float* betap  = (const float*)d_in[16];
    const float* Wp2    = (const float*)d_in[17];
    const float* bp2    = (const float*)d_in[18];
    const float* w_gl   = (const float*)d_in[19];
    const float* g_gl   = (const float*)d_in[20];
    const float* betagl = (const float*)d_in[21];
    const float* Wwe    = (const float*)d_in[22];
    const float* bwe    = (const float*)d_in[23];
    float* out = (float*)d_out;

    k_zero<<<5, 256>>>();
    dim3 gtc((NPTS + 127) / 128, 12);
    k_gemm_tc<<<gtc, 256>>>(feat, Wq, bq, Wk, bk, Wv, bv);
    k_stats_qk<<<256, 256>>>();
    k_posmom<<<NSROWS / 256, 256>>>(coord, ridx);
    k_final1<<<1, 256>>>(gq, betaq, gk, betak, Wp1, bp1, gp, betap, Wp2, bp2, w_gl);
    k_qkgroup<<<NPTS / 8, 256>>>(w_gl);
    k_wpre<<<(NSROWS + 1023) / 1024, 256>>>(coord, ridx, Wp1);
    k_wstats<<<512, 256>>>();
    k_final2<<<1, 32>>>(g_gl, betagl);
    k_pointG<<<NPTS, 256>>>(coord, ridx, Wp1, bp2, Wwe, bwe, out);
    dim3 gg2((NPTS + 127) / 128, 16);
    k_projH<<<gg2, 256>>>(Wp2, out);
}

// round 11
// speedup vs baseline: 1.1881x; 1.0630x over previous
#include <cuda_runtime.h>
#include <cuda_bf16.h>
#include <math.h>
#include <mma.h>

using namespace nvcuda;

#define NPTS 100000
#define SS 16
#define CC 256
#define GG 16
#define NSROWS (NPTS*SS)

// ---------------- scratch (__device__ globals, per harness rules) ----------------
__device__ float g_Qlin[NPTS*CC];
__device__ float g_Klin[NPTS*CC];
__device__ float g_V[NPTS*CC];
__device__ float g_qg[NPTS*GG];
__device__ float g_kg[NPTS*GG];
__device__ float g_wpre[NPTS*SS*GG];
__device__ float g_Hw[(size_t)NPTS*GG*CC];   // [n][g][c']  1.64 GB
__device__ __nv_bfloat16 g_featH[NPTS*CC];
__device__ __nv_bfloat16 g_featL[NPTS*CC];
__device__ __nv_bfloat16 g_WH[3*CC*CC];
__device__ __nv_bfloat16 g_WL[3*CC*CC];
__device__ double g_ds[1100];
// layout: 0 qsum[256], 256 qsq[256], 512 ksum[256], 768 ksq[256],
//         1024 posmom[9], 1040 wsum[16], 1056 wsq[16]
__device__ float g_aq[CC], g_bq[CC], g_ak[CC], g_bk[CC], g_ap[CC], g_bpf[CC];
__device__ float g_Wp2g[CC*GG];  // [c'][g]
__device__ float g_glb[GG];
__device__ float g_aw[GG], g_bw[GG];

// ---------------- K0: zero accumulators ----------------
__global__ void k_zero() {
    int t = blockIdx.x * 256 + threadIdx.x;
    if (t < 1100) g_ds[t] = 0.0;
}

// ---------------- bf16 hi/lo split helpers ----------------
__device__ __forceinline__ void split4(float4 v, __nv_bfloat162* h, __nv_bfloat162* l) {
    float xs[4] = {v.x, v.y, v.z, v.w};
    __nv_bfloat16 hh[4], ll[4];
#pragma unroll
    for (int i = 0; i < 4; i++) {
        hh[i] = __float2bfloat16_rn(xs[i]);
        ll[i] = __float2bfloat16_rn(xs[i] - __bfloat162float(hh[i]));
    }
    h[0] = __nv_bfloat162(hh[0], hh[1]);
    h[1] = __nv_bfloat162(hh[2], hh[3]);
    l[0] = __nv_bfloat162(ll[0], ll[1]);
    l[1] = __nv_bfloat162(ll[2], ll[3]);
}

// ---------------- K-cvt: one-time fp32 -> bf16 hi/lo ----------------
__global__ void k_cvt_feat(const float* __restrict__ feat) {
    size_t i = ((size_t)blockIdx.x * 256 + threadIdx.x) * 4;   // grid 25000, exact
    float4 v = *(const float4*)(feat + i);
    split4(v, (__nv_bfloat162*)(g_featH + i), (__nv_bfloat162*)(g_featL + i));
}

__global__ void k_cvt_W(const float* __restrict__ Wq, const float* __restrict__ Wk,
                        const float* __restrict__ Wv) {
    size_t i = ((size_t)blockIdx.x * 256 + threadIdx.x) * 4;   // grid 192, exact (196608)
    const float* W = (i < 65536) ? Wq : ((i < 131072) ? Wk : Wv);
    size_t off = i & 65535;
    float4 v = *(const float4*)(W + off);
    split4(v, (__nv_bfloat162*)(g_WH + i), (__nv_bfloat162*)(g_WL + i));
}

// ---------------- K1: QKV GEMM, bf16x3 split wmma, reg-prefetch pipeline ----------------
// fuses per-channel stats for Q (mat 0) and K (mat 1) into the epilogue
__global__ void __launch_bounds__(256) k_gemm_tc(
    const float* __restrict__ bq, const float* __restrict__ bk,
    const float* __restrict__ bv)
{
    __shared__ __align__(16) char sm[36864];
    __nv_bfloat16 (*Ah)[40] = (__nv_bfloat16(*)[40])(sm);
    __nv_bfloat16 (*Al)[40] = (__nv_bfloat16(*)[40])(sm + 10240);
    __nv_bfloat16 (*Bh)[72] = (__nv_bfloat16(*)[72])(sm + 20480);
    __nv_bfloat16 (*Bl)[72] = (__nv_bfloat16(*)[72])(sm + 25088);

    int mat = blockIdx.y >> 2;
    int n0  = (blockIdx.y & 3) << 6;
    int m0  = blockIdx.x << 7;
    const __nv_bfloat16* WH = g_WH + mat * 65536;
    const __nv_bfloat16* WL = g_WL + mat * 65536;
    const float* bias = (mat == 0) ? bq : ((mat == 1) ? bk : bv);
    float* out        = (mat == 0) ? g_Qlin : ((mat == 1) ? g_Klin : g_V);

    int t = threadIdx.x;
    int warp = t >> 5, lane = t & 31;
    int wm = warp & 3, wn = warp >> 2;

    // load mapping
    int arow = t >> 2, ac8 = (t & 3) * 8;     // A rows arow, arow+64
    int brow = t >> 3, bc8 = (t & 7) * 8;     // B row brow (0..31)
    int gm0 = m0 + arow;      if (gm0 >= NPTS) gm0 = NPTS - 1;
    int gm1 = m0 + arow + 64; if (gm1 >= NPTS) gm1 = NPTS - 1;

    wmma::fragment<wmma::accumulator, 16, 16, 16, float> acc[2][2];
#pragma unroll
    for (int i = 0; i < 2; i++)
#pragma unroll
        for (int j = 0; j < 2; j++) wmma::fill_fragment(acc[i][j], 0.f);

    uint4 rah0, rah1, ral0, ral1, rbh, rbl;
    // preload chunk 0
    {
        int k0 = 0;
        rah0 = *(const uint4*)(g_featH + (size_t)gm0 * CC + k0 + ac8);
        rah1 = *(const uint4*)(g_featH + (size_t)gm1 * CC + k0 + ac8);
        ral0 = *(const uint4*)(g_featL + (size_t)gm0 * CC + k0 + ac8);
        ral1 = *(const uint4*)(g_featL + (size_t)gm1 * CC + k0 + ac8);
        rbh  = *(const uint4*)(WH + (size_t)(k0 + brow) * CC + n0 + bc8);
        rbl  = *(const uint4*)(WL + (size_t)(k0 + brow) * CC + n0 + bc8);
    }
    *(uint4*)&Ah[arow][ac8]      = rah0;
    *(uint4*)&Ah[arow + 64][ac8] = rah1;
    *(uint4*)&Al[arow][ac8]      = ral0;
    *(uint4*)&Al[arow + 64][ac8] = ral1;
    *(uint4*)&Bh[brow][bc8]      = rbh;
    *(uint4*)&Bl[brow][bc8]      = rbl;
    __syncthreads();

    for (int c = 0; c < 8; c++) {
        if (c < 7) {   // prefetch next chunk into registers
            int k0 = (c + 1) * 32;
            rah0 = *(const uint4*)(g_featH + (size_t)gm0 * CC + k0 + ac8);
            rah1 = *(const uint4*)(g_featH + (size_t)gm1 * CC + k0 + ac8);
            ral0 = *(const uint4*)(g_featL + (size_t)gm0 * CC + k0 + ac8);
            ral1 = *(const uint4*)(g_featL + (size_t)gm1 * CC + k0 + ac8);
            rbh  = *(const uint4*)(WH + (size_t)(k0 + brow) * CC + n0 + bc8);
            rbl  = *(const uint4*)(WL + (size_t)(k0 + brow) * CC + n0 + bc8);
        }
#pragma unroll
        for (int kk = 0; kk < 32; kk += 16) {
            wmma::fragment<wmma::matrix_a, 16, 16, 16, __nv_bfloat16, wmma::row_major> ah[2], al[2];
            wmma::fragment<wmma::matrix_b, 16, 16, 16, __nv_bfloat16, wmma::row_major> bh[2], bl[2];
#pragma unroll
            for (int i = 0; i < 2; i++) {
                wmma::load_matrix_sync(ah[i], &Ah[wm * 32 + i * 16][kk], 40);
                wmma::load_matrix_sync(al[i], &Al[wm * 32 + i * 16][kk], 40);
                wmma::load_matrix_sync(bh[i], &Bh[kk][wn * 32 + i * 16], 72);
                wmma::load_matrix_sync(bl[i], &Bl[kk][wn * 32 + i * 16], 72);
            }
#pragma unroll
            for (int i = 0; i < 2; i++)
#pragma unroll
                for (int j = 0; j < 2; j++) {
                    wmma::mma_sync(acc[i][j], ah[i], bh[j], acc[i][j]);
                    wmma::mma_sync(acc[i][j], ah[i], bl[j], acc[i][j]);
                    wmma::mma_sync(acc[i][j], al[i], bh[j], acc[i][j]);
                }
        }
        __syncthreads();
        if (c < 7) {
            *(uint4*)&Ah[arow][ac8]      = rah0;
            *(uint4*)&Ah[arow + 64][ac8] = rah1;
            *(uint4*)&Al[arow][ac8]      = ral0;
            *(uint4*)&Al[arow + 64][ac8] = ral1;
            *(uint4*)&Bh[brow][bc8]      = rbh;
            *(uint4*)&Bl[brow][bc8]      = rbl;
            __syncthreads();
        }
    }

    // epilogue: stage via smem, add bias, store, fused q/k stats
    float (*ob)[36] = (float(*)[36])(sm + warp * 4608);
    float bb = bias[n0 + wn * 32 + lane];
#pragma unroll
    for (int i = 0; i < 2; i++) {
        wmma::store_matrix_sync(&ob[i * 16][0],  acc[i][0], 36, wmma::mem_row_major);
        wmma::store_matrix_sync(&ob[i * 16][16], acc[i][1], 36, wmma::mem_row_major);
    }
    __syncwarp();
    float s1 = 0.f, s2 = 0.f;
#pragma unroll
    for (int r = 0; r < 32; r++) {
        int gm = m0 + wm * 32 + r;
        if (gm < NPTS) {
            float v = ob[r][lane] + bb;
            out[(size_t)gm * CC + n0 + wn * 32 + lane] = v;
            s1 += v; s2 = fmaf(v, v, s2);
        }
    }
    if (mat < 2) {
        int base = (mat == 0) ? 0 : 512;
        int col = n0 + wn * 32 + lane;
        atomicAdd(&g_ds[base + col],       (double)s1);
        atomicAdd(&g_ds[base + 256 + col], (double)s2);
    }
}

// ---------------- K3: pos second moments ----------------
__global__ void k_posmom(const float* __restrict__ coord, const int* __restrict__ ridx) {
    int i = blockIdx.x * 256 + threadIdx.x;
    int n = i >> 4;
    int r = ridx[i];
    float px = 0, py = 0, pz = 0;
    if (r >= 0) {
        px = coord[r * 3 + 0] - coord[n * 3 + 0];
        py = coord[r * 3 + 1] - coord[n * 3 + 1];
        pz = coord[r * 3 + 2] - coord[n * 3 + 2];
    }
    float v[9] = {px, py, pz, px * px, py * py, pz * pz, px * py, px * pz, py * pz};
    __shared__ float red[8][9];
    int lane = threadIdx.x & 31, w = threadIdx.x >> 5;
#pragma unroll
    for (int j = 0; j < 9; j++)
#pragma unroll
        for (int off = 16; off; off >>= 1)
            v[j] += __shfl_down_sync(0xffffffffu, v[j], off);
    if (lane == 0)
#pragma unroll
        for (int j = 0; j < 9; j++) red[w][j] = v[j];
    __syncthreads();
    if (threadIdx.x < 9) {
        float s = 0;
        for (int w2 = 0; w2 < 8; w2++) s += red[w2][threadIdx.x];
        atomicAdd(&g_ds[1024 + threadIdx.x], (double)s);
    }
}

// ---------------- K4: fold BN params; build Wp2g, glb ----------------
__global__ void k_final1(
    const float* __restrict__ gq, const float* __restrict__ betaq,
    const float* __restrict__ gk, const float* __restrict__ betak,
    const float* __restrict__ Wp1, const float* __restrict__ bp1,
    const float* __restrict__ gp, const float* __restrict__ betap,
    const float* __restrict__ Wp2, const float* __restrict__ bp2,
    const float* __restrict__ w_gl)
{
    int c = threadIdx.x;
    double invN = 1.0 / (double)NPTS;
    {
        double mu = g_ds[c] * invN;
        double var = g_ds[256 + c] * invN - mu * mu;
        float a = (float)((double)gq[c] / sqrt(var + 1e-5));
        g_aq[c] = a; g_bq[c] = betaq[c] - (float)mu * a;
    }
    {
        double mu = g_ds[512 + c] * invN;
        double var = g_ds[768 + c] * invN - mu * mu;
        float a = (float)((double)gk[c] / sqrt(var + 1e-5));
        g_ak[c] = a; g_bk[c] = betak[c] - (float)mu * a;
    }
    {
        double sx = g_ds[1024], sy = g_ds[1025], sz = g_ds[1026];
        double xx = g_ds[1027], yy = g_ds[1028], zz = g_ds[1029];
        double xy = g_ds[1030], xz = g_ds[1031], yz = g_ds[1032];
        double w0 = Wp1[c], w1 = Wp1[256 + c], w2 = Wp1[512 + c], b = bp1[c];
        double invNS = 1.0 / (double)NSROWS;
        double sw = sx * w0 + sy * w1 + sz * w2;
        double mean = sw * invNS + b;
        double ex2 = (w0 * w0 * xx + w1 * w1 * yy + w2 * w2 * zz
                      + 2.0 * (w0 * w1 * xy + w0 * w2 * xz + w1 * w2 * yz)
                      + 2.0 * b * sw) * invNS + b * b;
        double var = ex2 - mean * mean;
        float a = (float)((double)gp[c] / sqrt(var + 1e-5));
        g_ap[c]  = a;
        g_bpf[c] = (float)((double)a * b + (double)betap[c] - mean * a);
    }
#pragma unroll
    for (int g = 0; g < GG; g++) {
        float s = 0;
#pragma unroll
        for (int i2 = 0; i2 < 16; i2++)
            s = fmaf(Wp2[(size_t)c * CC + g * 16 + i2], w_gl[g * 16 + i2], s);
        g_Wp2g[c * GG + g] = s;
    }
    if (c < GG) {
        float s = 0;
#pragma unroll
        for (int i2 = 0; i2 < 16; i2++) s = fmaf(bp2[c * 16 + i2], w_gl[c * 16 + i2], s);
        g_glb[c] = s;
    }
}

// ---------------- K5: group-folded q,k vectors ----------------
__global__ void __launch_bounds__(256) k_qkgroup(const float* __restrict__ w_gl) {
    int lane = threadIdx.x & 31, warp = threadIdx.x >> 5;
    int n = blockIdx.x * 8 + warp;
#pragma unroll
    for (int j = 0; j < 8; j++) {
        int c = lane + 32 * j;
        float wg = w_gl[c];
        float vq = fmaxf(fmaf(g_aq[c], g_Qlin[(size_t)n * CC + c], g_bq[c]), 0.f) * wg;
        float vk = fmaxf(fmaf(g_ak[c], g_Klin[(size_t)n * CC + c], g_bk[c]), 0.f) * wg;
#pragma unroll
        for (int off = 8; off; off >>= 1) {
            vq += __shfl_down_sync(0xffffffffu, vq, off, 16);
            vk += __shfl_down_sync(0xffffffffu, vk, off, 16);
        }
        if (lane == 0)  { g_qg[n * GG + 2 * j]     = vq; g_kg[n * GG + 2 * j]     = vk; }
        if (lane == 16) { g_qg[n * GG + 2 * j + 1] = vq; g_kg[n * GG + 2 * j + 1] = vk; }
    }
}

// ---------------- K6: w_pre logits (float4 broadcast loads) ----------------
__global__ void __launch_bounds__(256, 1) k_wpre(
    const float* __restrict__ coord, const int* __restrict__ ridx,
    const float* __restrict__ Wp1)
{
    __shared__ __align__(16) float Bs[256][16];
    __shared__ __align__(16) float4 P4[256];
    __shared__ float Bpf[256];
    __shared__ float glb_s[16];
    int t = threadIdx.x;
    for (int l = t; l < 4096; l += 256) Bs[l >> 4][l & 15] = g_Wp2g[l];
    P4[t] = make_float4(Wp1[t], Wp1[256 + t], Wp1[512 + t], g_ap[t]);
    Bpf[t] = g_bpf[t];
    if (t < 16) glb_s[t] = g_glb[t];
    __syncthreads();

    int base = blockIdx.x * 1024;
    int rw[4];
    float px[4], py[4], pz[4];
#pragma unroll
    for (int q = 0; q < 4; q++) {
        int row = base + t + q * 256;
        int r = -1;
        float x = 0, y = 0, z = 0;
        if (row < NSROWS) {
            r = ridx[row];
            if (r >= 0) {
                int n = row >> 4;
                x = coord[r * 3 + 0] - coord[n * 3 + 0];
                y = coord[r * 3 + 1] - coord[n * 3 + 1];
                z = coord[r * 3 + 2] - coord[n * 3 + 2];
            }
        }
        rw[q] = r; px[q] = x; py[q] = y; pz[q] = z;
    }

    float acc[4][16];
#pragma unroll
    for (int q = 0; q < 4; q++)
#pragma unroll
        for (int g = 0; g < 16; g++) acc[q][g] = 0.f;

    for (int k = 0; k < 256; k++) {
        float4 pk = P4[k];
        float bp = Bpf[k];
        float h[4];
#pragma unroll
        for (int q = 0; q < 4; q++) {
            float pd = fmaf(pz[q], pk.z, fmaf(py[q], pk.y, px[q] * pk.x));
            h[q] = fmaxf(fmaf(pk.w, pd, bp), 0.f);
        }
        float4 b0 = *(const float4*)&Bs[k][0];
        float4 b1 = *(const float4*)&Bs[k][4];
        float4 b2 = *(const float4*)&Bs[k][8];
        float4 b3 = *(const float4*)&Bs[k][12];
#pragma unroll
        for (int q = 0; q < 4; q++) {
            acc[q][0]  = fmaf(h[q], b0.x, acc[q][0]);
            acc[q][1]  = fmaf(h[q], b0.y, acc[q][1]);
            acc[q][2]  = fmaf(h[q], b0.z, acc[q][2]);
            acc[q][3]  = fmaf(h[q], b0.w, acc[q][3]);
            acc[q][4]  = fmaf(h[q], b1.x, acc[q][4]);
            acc[q][5]  = fmaf(h[q], b1.y, acc[q][5]);
            acc[q][6]  = fmaf(h[q], b1.z, acc[q][6]);
            acc[q][7]  = fmaf(h[q], b1.w, acc[q][7]);
            acc[q][8]  = fmaf(h[q], b2.x, acc[q][8]);
            acc[q][9]  = fmaf(h[q], b2.y, acc[q][9]);
            acc[q][10] = fmaf(h[q], b2.z, acc[q][10]);
            acc[q][11] = fmaf(h[q], b2.w, acc[q][11]);
            acc[q][12] = fmaf(h[q], b3.x, acc[q][12]);
            acc[q][13] = fmaf(h[q], b3.y, acc[q][13]);
            acc[q][14] = fmaf(h[q], b3.z, acc[q][14]);
            acc[q][15] = fmaf(h[q], b3.w, acc[q][15]);
        }
    }

#pragma unroll
    for (int q = 0; q < 4; q++) {
        int row = base + t + q * 256;
        if (row < NSROWS) {
            int n = row >> 4;
            int r = rw[q];
#pragma unroll
            for (int g = 0; g < 16; g++) {
                float kgv = (r >= 0) ? g_kg[(size_t)r * GG + g] : 0.f;
                g_wpre[(size_t)row * GG + g] =
                    kgv - g_qg[(size_t)n * GG + g] + acc[q][g] + glb_s[g];
            }
        }
    }
}

// ---------------- K7: group stats of w_pre ----------------
__global__ void k_wstats() {
    __shared__ float ssum[16], ssq[16];
    int t = threadIdx.x;
    if (t < 16) { ssum[t] = 0.f; ssq[t] = 0.f; }
    __syncthreads();
    int g = t & 15;
    float s1 = 0, s2 = 0;
    for (int row = blockIdx.x * 16 + (t >> 4); row < NSROWS; row += gridDim.x * 16) {
        float x = g_wpre[(size_t)row * GG + g];
        s1 += x; s2 = fmaf(x, x, s2);
    }
    atomicAdd(&ssum[g], s1);
    atomicAdd(&ssq[g], s2);
    __syncthreads();
    if (t < 16) {
        atomicAdd(&g_ds[1040 + t], (double)ssum[t]);
        atomicAdd(&g_ds[1056 + t], (double)ssq[t]);
    }
}

// ---------------- K8: fold group BN ----------------
__global__ void k_final2(const float* __restrict__ g_gl, const float* __restrict__ beta_gl) {
    int g = threadIdx.x;
    if (g < 16) {
        double invNS = 1.0 / (double)NSROWS;
        double mu  = g_ds[1040 + g] * invNS;
        double var = g_ds[1056 + g] * invNS - mu * mu;
        float a = (float)((double)g_gl[g] / sqrt(var + 1e-5));
        g_aw[g] = a; g_bw[g] = beta_gl[g] - (float)mu * a;
    }
}

// ---------------- K9: fused per-point: logits -> softmax -> gathered V + Hw ----------------
__global__ void __launch_bounds__(256) k_pointG(
    const float* __restrict__ coord, const int* __restrict__ ridx,
    const float* __restrict__ Wp1,  const float* __restrict__ bp2,
    const float* __restrict__ Wwe,  const float* __restrict__ bwe,
    float* __restrict__ out)
{
    __shared__ float rl[16][17];
    __shared__ float lg[16][17];
    __shared__ float wsm[16][17];
    __shared__ float wsum[16];
    __shared__ float Wwe_s[16][16];
    __shared__ float bwe_s[16];
    __shared__ float psx[16], psy[16], psz[16];
    __shared__ int   rs[16];

    int n = blockIdx.x, t = threadIdx.x;
    Wwe_s[t >> 4][t & 15] = Wwe[t];
    if (t < 16) {
        bwe_s[t] = bwe[t];
        int r = ridx[n * SS + t];
        rs[t] = r;
        float x = 0, y = 0, z = 0;
        if (r >= 0) {
            x = coord[r * 3 + 0] - coord[n * 3 + 0];
            y = coord[r * 3 + 1] - coord[n * 3 + 1];
            z = coord[r * 3 + 2] - coord[n * 3 + 2];
        }
        psx[t] = x; psy[t] = y; psz[t] = z;
    }
    int s = t >> 4, g = t & 15;
    {
        float x = g_wpre[(size_t)n * 256 + t];
        rl[s][g] = fmaxf(fmaf(g_aw[g], x, g_bw[g]), 0.f);
    }
    __syncthreads();
    {
        float acc = bwe_s[g];
#pragma unroll
        for (int gp2 = 0; gp2 < 16; gp2++)
            acc = fmaf(rl[s][gp2], Wwe_s[gp2][g], acc);
        lg[s][g] = acc;
    }
    __syncthreads();
    if (t < 16) {
        float m = -1e30f;
#pragma unroll
        for (int ss2 = 0; ss2 < 16; ss2++) m = fmaxf(m, lg[ss2][t]);
        float sum = 0;
        float e[16];
#pragma unroll
        for (int ss2 = 0; ss2 < 16; ss2++) { e[ss2] = expf(lg[ss2][t] - m); sum += e[ss2]; }
        float inv = 1.f / sum;
        float ws = 0;
#pragma unroll
        for (int ss2 = 0; ss2 < 16; ss2++) {
            float w = (rs[ss2] >= 0) ? e[ss2] * inv : 0.f;
            wsm[ss2][t] = w; ws += w;
        }
        wsum[t] = ws;
    }
    __syncthreads();

    int c = t, gc = c >> 4;
    float hw[16];
#pragma unroll
    for (int gg = 0; gg < 16; gg++) hw[gg] = 0.f;
    float out1 = wsum[gc] * bp2[c];
    float w1c = Wp1[c], w2c = Wp1[256 + c], w3c = Wp1[512 + c];
    float apc = g_ap[c], bpc = g_bpf[c];
#pragma unroll
    for (int ss2 = 0; ss2 < 16; ss2++) {
        int r = rs[ss2];
        if (r >= 0) {
            out1 = fmaf(wsm[ss2][gc], g_V[(size_t)r * CC + c], out1);
            float pd = fmaf(psz[ss2], w3c, fmaf(psy[ss2], w2c, psx[ss2] * w1c));
            float h = fmaxf(fmaf(apc, pd, bpc), 0.f);
#pragma unroll
            for (int gg = 0; gg < 16; gg++)
                hw[gg] = fmaf(wsm[ss2][gg], h, hw[gg]);
        }
    }
    out[(size_t)n * CC + c] = out1;
#pragma unroll
    for (int gg = 0; gg < 16; gg++)
        g_Hw[(size_t)n * 4096 + gg * 256 + c] = hw[gg];
}

// ---------------- K10: projection GEMM, 2x4 micro-kernel, float4 B ----------------
__global__ void __launch_bounds__(256) k_projH(
    const float* __restrict__ Wp2, float* __restrict__ out)
{
    __shared__ __align__(16) float Bs[256][20];
    __shared__ __align__(16) float As[128][36];
    int g = blockIdx.y;
    int n0 = blockIdx.x * 128;
    int t = threadIdx.x;
    for (int l = t; l < 4096; l += 256)
        Bs[l >> 4][l & 15] = Wp2[(size_t)(l >> 4) * CC + g * 16 + (l & 15)];

    int j0 = (t & 3) * 4;
    int rp = t >> 2;          // rows rp and rp+64
    float a00 = 0, a01 = 0, a02 = 0, a03 = 0;
    float a10 = 0, a11 = 0, a12 = 0, a13 = 0;

    for (int kc = 0; kc < 8; kc++) {
        int k0 = kc * 32;
        __syncthreads();
        // stage As: 128 x 32 floats via float4 (4 per thread)
#pragma unroll
        for (int l = t; l < 1024; l += 256) {
            int row = l >> 3, c4 = (l & 7) * 4;
            int nn = n0 + row;
            float4 v = (nn < NPTS)
                ? *(const float4*)(g_Hw + (size_t)nn * 4096 + g * 256 + k0 + c4)
                : make_float4(0.f, 0.f, 0.f, 0.f);
            *(float4*)&As[row][c4] = v;
        }
        __syncthreads();
#pragma unroll
        for (int kk = 0; kk < 32; kk++) {
            float4 b = *(const float4*)&Bs[k0 + kk][j0];
            float a0 = As[rp][kk];
            float a1 = As[rp + 64][kk];
            a00 = fmaf(a0, b.x, a00); a01 = fmaf(a0, b.y, a01);
            a02 = fmaf(a0, b.z, a02); a03 = fmaf(a0, b.w, a03);
            a10 = fmaf(a1, b.x, a10); a11 = fmaf(a1, b.y, a11);
            a12 = fmaf(a1, b.z, a12); a13 = fmaf(a1, b.w, a13);
        }
    }
    {
        int nn = n0 + rp;
        if (nn < NPTS) {
            float4* p = (float4*)(out + (size_t)nn * CC + g * 16 + j0);
            float4 cur = *p;
            cur.x += a00; cur.y += a01; cur.z += a02; cur.w += a03;
            *p = cur;
        }
    }
    {
        int nn = n0 + rp + 64;
        if (nn < NPTS) {
            float4* p = (float4*)(out + (size_t)nn * CC + g * 16 + j0);
            float4 cur = *p;
            cur.x += a10; cur.y += a11; cur.z += a12; cur.w += a13;
            *p = cur;
        }
    }
}

// ---------------- launch ----------------
extern "C" void kernel_launch(void* const* d_in, const int* in_sizes, int n_in,
                              void* d_out, int out_size) {
    const float* feat   = (const float*)d_in[0];
    const float* coord  = (const float*)d_in[1];
    const int*   ridx   = (const int*)  d_in[2];
    const float* Wq     = (const float*)d_in[3];
    const float* bq     = (const float*)d_in[4];
    const float* gq     = (const float*)d_in[5];
    const float* betaq  = (const float*)d_in[6];
    const float* Wk     = (const float*)d_in[7];
    const float* bk     = (const float*)d_in[8];
    const float* gk     = (const float*)d_in[9];
    const float* betak  = (const float*)d_in[10];
    const float* Wv     = (const float*)d_in[11];
    const float* bv     = (const float*)d_in[12];
    const float* Wp1    = (const float*)d_in[13];
    const float* bp1    = (const float*)d_in[14];
    const float* gp     = (const float*)d_in[15];
    const float* betap  = (const float*)d_in[16];
    const float* Wp2    = (const float*)d_in[17];
    const float* bp2    = (const float*)d_in[18];
    const float* w_gl   = (const float*)d_in[19];
    const float* g_gl   = (const float*)d_in[20];
    const float* betagl = (const float*)d_in[21];
    const float* Wwe    = (const float*)d_in[22];
    const float* bwe    = (const float*)d_in[23];
    float* out = (float*)d_out;

    k_zero<<<5, 256>>>();
    k_cvt_feat<<<25000, 256>>>(feat);
    k_cvt_W<<<192, 256>>>(Wq, Wk, Wv);
    dim3 gtc((NPTS + 127) / 128, 12);
    k_gemm_tc<<<gtc, 256>>>(bq, bk, bv);
    k_posmom<<<NSROWS / 256, 256>>>(coord, ridx);
    k_final1<<<1, 256>>>(gq, betaq, gk, betak, Wp1, bp1, gp, betap, Wp2, bp2, w_gl);
    k_qkgroup<<<NPTS / 8, 256>>>(w_gl);
    k_wpre<<<(NSROWS + 1023) / 1024, 256>>>(coord, ridx, Wp1);
    k_wstats<<<512, 256>>>();
    k_final2<<<1, 32>>>(g_gl, betagl);
    k_pointG<<<NPTS, 256>>>(coord, ridx, Wp1, bp2, Wwe, bwe, out);
    dim3 gg2((NPTS + 127) / 128, 16);
    k_projH<<<gg2, 256>>>(Wp2, out);
}

// round 14
// speedup vs baseline: 1.3347x; 1.1234x over previous
#include <cuda_runtime.h>
#include <cuda_bf16.h>
#include <math.h>
#include <mma.h>
#include <cstdint>

using namespace nvcuda;

#define NPTS 100000
#define SS 16
#define CC 256
#define GG 16
#define NSROWS (NPTS*SS)

// ---------------- scratch (__device__ globals, per harness rules) ----------------
__device__ float g_Qlin[NPTS*CC];
__device__ float g_Klin[NPTS*CC];
__device__ float g_V[NPTS*CC];
__device__ float g_qg[NPTS*GG];
__device__ float g_kg[NPTS*GG];
__device__ float g_wpre[NPTS*SS*GG];
__device__ float g_Hw[(size_t)NPTS*GG*CC];   // [n][g][c']  1.64 GB
__device__ __nv_bfloat16 g_featH[NPTS*CC];
__device__ __nv_bfloat16 g_featL[NPTS*CC];
__device__ __nv_bfloat16 g_WH[3*CC*CC];
__device__ __nv_bfloat16 g_WL[3*CC*CC];
__device__ double g_ds[1100];
// layout: 0 qsum[256], 256 qsq[256], 512 ksum[256], 768 ksq[256],
//         1024 posmom[9], 1040 wsum[16], 1056 wsq[16]
__device__ float g_aq[CC], g_bq[CC], g_ak[CC], g_bk[CC], g_ap[CC], g_bpf[CC];
__device__ float g_Wp2g[CC*GG];  // [c'][g]
__device__ float g_glb[GG];
__device__ float g_aw[GG], g_bw[GG];

// ---------------- K0: zero accumulators ----------------
__global__ void k_zero() {
    int t = blockIdx.x * 256 + threadIdx.x;
    if (t < 1100) g_ds[t] = 0.0;
}

// ---------------- bf16 hi/lo split helpers ----------------
__device__ __forceinline__ void split4(float4 v, __nv_bfloat162* h, __nv_bfloat162* l) {
    float xs[4] = {v.x, v.y, v.z, v.w};
    __nv_bfloat16 hh[4], ll[4];
#pragma unroll
    for (int i = 0; i < 4; i++) {
        hh[i] = __float2bfloat16_rn(xs[i]);
        ll[i] = __float2bfloat16_rn(xs[i] - __bfloat162float(hh[i]));
    }
    h[0] = __nv_bfloat162(hh[0], hh[1]);
    h[1] = __nv_bfloat162(hh[2], hh[3]);
    l[0] = __nv_bfloat162(ll[0], ll[1]);
    l[1] = __nv_bfloat162(ll[2], ll[3]);
}

// ---------------- K-cvt: one-time fp32 -> bf16 hi/lo ----------------
__global__ void k_cvt_feat(const float* __restrict__ feat) {
    size_t i = ((size_t)blockIdx.x * 256 + threadIdx.x) * 4;   // grid 25000, exact
    float4 v = *(const float4*)(feat + i);
    split4(v, (__nv_bfloat162*)(g_featH + i), (__nv_bfloat162*)(g_featL + i));
}

__global__ void k_cvt_W(const float* __restrict__ Wq, const float* __restrict__ Wk,
                        const float* __restrict__ Wv) {
    size_t i = ((size_t)blockIdx.x * 256 + threadIdx.x) * 4;   // grid 192, exact (196608)
    const float* W = (i < 65536) ? Wq : ((i < 131072) ? Wk : Wv);
    size_t off = i & 65535;
    float4 v = *(const float4*)(W + off);
    split4(v, (__nv_bfloat162*)(g_WH + i), (__nv_bfloat162*)(g_WL + i));
}

// ---------------- cp.async helpers ----------------
__device__ __forceinline__ void cp16(void* dst, const void* src) {
    unsigned int d = (unsigned int)__cvta_generic_to_shared(dst);
    asm volatile("cp.async.cg.shared.global [%0], [%1], 16;\n" :: "r"(d), "l"(src));
}
__device__ __forceinline__ void cp_commit() {
    asm volatile("cp.async.commit_group;\n");
}
template <int N>
__device__ __forceinline__ void cp_wait() {
    asm volatile("cp.async.wait_group %0;\n" :: "n"(N));
}

// ---------------- K1: QKV GEMM, bf16x3 split wmma ----------------
// 128x128 block tile, 8 warps of 32x64, cp.async double-buffered, 2 CTAs/SM.
// Fuses per-channel stats for Q (mat 0) and K (mat 1) into the epilogue.
// Dynamic smem layout per stage (37888 B):
//   Ah[128][40] @0, Al[128][40] @10240, Bh[32][136] @20480, Bl[32][136] @29184
#define STG_BYTES 37888
#define GEMM_SMEM (2*STG_BYTES)

__global__ void __launch_bounds__(256, 2) k_gemm_tc(
    const float* __restrict__ bq, const float* __restrict__ bk,
    const float* __restrict__ bv)
{
    extern __shared__ __align__(16) char sm[];

    int mat = blockIdx.y >> 1;
    int n0  = (blockIdx.y & 1) << 7;
    int m0  = blockIdx.x << 7;
    const __nv_bfloat16* WH = g_WH + mat * 65536;
    const __nv_bfloat16* WL = g_WL + mat * 65536;
    const float* bias = (mat == 0) ? bq : ((mat == 1) ? bk : bv);
    float* out        = (mat == 0) ? g_Qlin : ((mat == 1) ? g_Klin : g_V);

    int t = threadIdx.x;
    int warp = t >> 5, lane = t & 31;
    int wm = warp & 3, wn = warp >> 2;     // warp tile: rows wm*32, cols wn*64

    int ar0 = t >> 2,        ac = (t & 3) * 8;      // A rows ar0, ar0+64
    int br0 = t >> 4,        bc = (t & 15) * 8;     // B rows br0, br0+16
    int gm0 = m0 + ar0;       if (gm0 >= NPTS) gm0 = NPTS - 1;
    int gm1 = m0 + ar0 + 64;  if (gm1 >= NPTS) gm1 = NPTS - 1;

    wmma::fragment<wmma::accumulator, 16, 16, 16, float> acc[2][4];
#pragma unroll
    for (int i = 0; i < 2; i++)
#pragma unroll
        for (int j = 0; j < 4; j++) wmma::fill_fragment(acc[i][j], 0.f);

    auto issue = [&](int c, int s) {
        char* base = sm + s * STG_BYTES;
        __nv_bfloat16 (*Ah)[40]  = (__nv_bfloat16(*)[40])(base);
        __nv_bfloat16 (*Al)[40]  = (__nv_bfloat16(*)[40])(base + 10240);
        __nv_bfloat16 (*Bh)[136] = (__nv_bfloat16(*)[136])(base + 20480);
        __nv_bfloat16 (*Bl)[136] = (__nv_bfloat16(*)[136])(base + 29184);
        int k0 = c * 32;
        cp16(&Ah[ar0][ac],      g_featH + (size_t)gm0 * CC + k0 + ac);
        cp16(&Ah[ar0 + 64][ac], g_featH + (size_t)gm1 * CC + k0 + ac);
        cp16(&Al[ar0][ac],      g_featL + (size_t)gm0 * CC + k0 + ac);
        cp16(&Al[ar0 + 64][ac], g_featL + (size_t)gm1 * CC + k0 + ac);
        cp16(&Bh[br0][bc],      WH + (size_t)(k0 + br0) * CC + n0 + bc);
        cp16(&Bh[br0 + 16][bc], WH + (size_t)(k0 + br0 + 16) * CC + n0 + bc);
        cp16(&Bl[br0][bc],      WL + (size_t)(k0 + br0) * CC + n0 + bc);
        cp16(&Bl[br0 + 16][bc], WL + (size_t)(k0 + br0 + 16) * CC + n0 + bc);
        cp_commit();
    };

    issue(0, 0);
    issue(1, 1);

    for (int c = 0; c < 8; c++) {
        // Drain fix: on the LAST chunk no younger group exists, so allowing
        // one pending group (wait<1>) would let chunk 7 itself stay in flight.
        if (c + 1 < 8) cp_wait<1>(); else cp_wait<0>();
        __syncthreads();
        char* base = sm + (c & 1) * STG_BYTES;
        __nv_bfloat16 (*Ah)[40]  = (__nv_bfloat16(*)[40])(base);
        __nv_bfloat16 (*Al)[40]  = (__nv_bfloat16(*)[40])(base + 10240);
        __nv_bfloat16 (*Bh)[136] = (__nv_bfloat16(*)[136])(base + 20480);
        __nv_bfloat16 (*Bl)[136] = (__nv_bfloat16(*)[136])(base + 29184);
#pragma unroll
        for (int kk = 0; kk < 32; kk += 16) {
            wmma::fragment<wmma::matrix_a, 16, 16, 16, __nv_bfloat16, wmma::row_major> ah[2], al[2];
#pragma unroll
            for (int i = 0; i < 2; i++) {
                wmma::load_matrix_sync(ah[i], &Ah[wm * 32 + i * 16][kk], 40);
                wmma::load_matrix_sync(al[i], &Al[wm * 32 + i * 16][kk], 40);
            }
#pragma unroll
            for (int j = 0; j < 4; j++) {
                wmma::fragment<wmma::matrix_b, 16, 16, 16, __nv_bfloat16, wmma::row_major> bh, bl;
                wmma::load_matrix_sync(bh, &Bh[kk][wn * 64 + j * 16], 136);
                wmma::load_matrix_sync(bl, &Bl[kk][wn * 64 + j * 16], 136);
#pragma unroll
                for (int i = 0; i < 2; i++) {
                    wmma::mma_sync(acc[i][j], ah[i], bh, acc[i][j]);
                    wmma::mma_sync(acc[i][j], ah[i], bl, acc[i][j]);
                    wmma::mma_sync(acc[i][j], al[i], bh, acc[i][j]);
                }
            }
        }
        __syncthreads();
        if (c + 2 < 8) issue(c + 2, c & 1);
    }

    // epilogue: per-warp smem staging (32x68 floats = 8704 B each), bias, stats
    float (*ob)[68] = (float(*)[68])(sm + warp * 8704);
#pragma unroll
    for (int i = 0; i < 2; i++)
#pragma unroll
        for (int j = 0; j < 4; j++)
            wmma::store_matrix_sync(&ob[i * 16][j * 16], acc[i][j], 68, wmma::mem_row_major);
    __syncwarp();

    int col0 = n0 + wn * 64 + lane;
    int col1 = col0 + 32;
    float bb0 = bias[col0], bb1 = bias[col1];
    float s1a = 0.f, s2a = 0.f, s1b = 0.f, s2b = 0.f;
#pragma unroll
    for (int r = 0; r < 32; r++) {
        int gm = m0 + wm * 32 + r;
        if (gm < NPTS) {
            float v0 = ob[r][lane] + bb0;
            float v1 = ob[r][lane + 32] + bb1;
            out[(size_t)gm * CC + col0] = v0;
            out[(size_t)gm * CC + col1] = v1;
            s1a += v0; s2a = fmaf(v0, v0, s2a);
            s1b += v1; s2b = fmaf(v1, v1, s2b);
        }
    }
    if (mat < 2) {
        int base = (mat == 0) ? 0 : 512;
        atomicAdd(&g_ds[base + col0],       (double)s1a);
        atomicAdd(&g_ds[base + 256 + col0], (double)s2a);
        atomicAdd(&g_ds[base + col1],       (double)s1b);
        atomicAdd(&g_ds[base + 256 + col1], (double)s2b);
    }
}

// ---------------- K3: pos second moments ----------------
__global__ void k_posmom(const float* __restrict__ coord, const int* __restrict__ ridx) {
    int i = blockIdx.x * 256 + threadIdx.x;
    int n = i >> 4;
    int r = ridx[i];
    float px = 0, py = 0, pz = 0;
    if (r >= 0) {
        px = coord[r * 3 + 0] - coord[n * 3 + 0];
        py = coord[r * 3 + 1] - coord[n * 3 + 1];
        pz = coord[r * 3 + 2] - coord[n * 3 + 2];
    }
    float v[9] = {px, py, pz, px * px, py * py, pz * pz, px * py, px * pz, py * pz};
    __shared__ float red[8][9];
    int lane = threadIdx.x & 31, w = threadIdx.x >> 5;
#pragma unroll
    for (int j = 0; j < 9; j++)
#pragma unroll
        for (int off = 16; off; off >>= 1)
            v[j] += __shfl_down_sync(0xffffffffu, v[j], off);
    if (lane == 0)
#pragma unroll
        for (int j = 0; j < 9; j++) red[w][j] = v[j];
    __syncthreads();
    if (threadIdx.x < 9) {
        float s = 0;
        for (int w2 = 0; w2 < 8; w2++) s += red[w2][threadIdx.x];
        atomicAdd(&g_ds[1024 + threadIdx.x], (double)s);
    }
}

// ---------------- K4: fold BN params; build Wp2g, glb ----------------
__global__ void k_final1(
    const float* __restrict__ gq, const float* __restrict__ betaq,
    const float* __restrict__ gk, const float* __restrict__ betak,
    const float* __restrict__ Wp1, const float* __restrict__ bp1,
    const float* __restrict__ gp, const float* __restrict__ betap,
    const float* __restrict__ Wp2, const float* __restrict__ bp2,
    const float* __restrict__ w_gl)
{
    int c = threadIdx.x;
    double invN = 1.0 / (double)NPTS;
    {
        double mu = g_ds[c] * invN;
        double var = g_ds[256 + c] * invN - mu * mu;
        float a = (float)((double)gq[c] / sqrt(var + 1e-5));
        g_aq[c] = a; g_bq[c] = betaq[c] - (float)mu * a;
    }
    {
        double mu = g_ds[512 + c] * invN;
        double var = g_ds[768 + c] * invN - mu * mu;
        float a = (float)((double)gk[c] / sqrt(var + 1e-5));
        g_ak[c] = a; g_bk[c] = betak[c] - (float)mu * a;
    }
    {
        double sx = g_ds[1024], sy = g_ds[1025], sz = g_ds[1026];
        double xx = g_ds[1027], yy = g_ds[1028], zz = g_ds[1029];
        double xy = g_ds[1030], xz = g_ds[1031], yz = g_ds[1032];
        double w0 = Wp1[c], w1 = Wp1[256 + c], w2 = Wp1[512 + c], b = bp1[c];
        double invNS = 1.0 / (double)NSROWS;
        double sw = sx * w0 + sy * w1 + sz * w2;
        double mean = sw * invNS + b;
        double ex2 = (w0 * w0 * xx + w1 * w1 * yy + w2 * w2 * zz
                      + 2.0 * (w0 * w1 * xy + w0 * w2 * xz + w1 * w2 * yz)
                      + 2.0 * b * sw) * invNS + b * b;
        double var = ex2 - mean * mean;
        float a = (float)((double)gp[c] / sqrt(var + 1e-5));
        g_ap[c]  = a;
        g_bpf[c] = (float)((double)a * b + (double)betap[c] - mean * a);
    }
#pragma unroll
    for (int g = 0; g < GG; g++) {
        float s = 0;
#pragma unroll
        for (int i2 = 0; i2 < 16; i2++)
            s = fmaf(Wp2[(size_t)c * CC + g * 16 + i2], w_gl[g * 16 + i2], s);
        g_Wp2g[c * GG + g] = s;
    }
    if (c < GG) {
        float s = 0;
#pragma unroll
        for (int i2 = 0; i2 < 16; i2++) s = fmaf(bp2[c * 16 + i2], w_gl[c * 16 + i2], s);
        g_glb[c] = s;
    }
}

// ---------------- K5: group-folded q,k vectors ----------------
__global__ void __launch_bounds__(256) k_qkgroup(const float* __restrict__ w_gl) {
    int lane = threadIdx.x & 31, warp = threadIdx.x >> 5;
    int n = blockIdx.x * 8 + warp;
#pragma unroll
    for (int j = 0; j < 8; j++) {
        int c = lane + 32 * j;
        float wg = w_gl[c];
        float vq = fmaxf(fmaf(g_aq[c], g_Qlin[(size_t)n * CC + c], g_bq[c]), 0.f) * wg;
        float vk = fmaxf(fmaf(g_ak[c], g_Klin[(size_t)n * CC + c], g_bk[c]), 0.f) * wg;
#pragma unroll
        for (int off = 8; off; off >>= 1) {
            vq += __shfl_down_sync(0xffffffffu, vq, off, 16);
            vk += __shfl_down_sync(0xffffffffu, vk, off, 16);
        }
        if (lane == 0)  { g_qg[n * GG + 2 * j]     = vq; g_kg[n * GG + 2 * j]     = vk; }
        if (lane == 16) { g_qg[n * GG + 2 * j + 1] = vq; g_kg[n * GG + 2 * j + 1] = vk; }
    }
}

// ---------------- K6: w_pre logits (float4 broadcast loads) ----------------
__global__ void __launch_bounds__(256, 1) k_wpre(
    const float* __restrict__ coord, const int* __restrict__ ridx,
    const float* __restrict__ Wp1)
{
    __shared__ __align__(16) float Bs[256][16];
    __shared__ __align__(16) float4 P4[256];
    __shared__ float Bpf[256];
    __shared__ float glb_s[16];
    int t = threadIdx.x;
    for (int l = t; l < 4096; l += 256) Bs[l >> 4][l & 15] = g_Wp2g[l];
    P4[t] = make_float4(Wp1[t], Wp1[256 + t], Wp1[512 + t], g_ap[t]);
    Bpf[t] = g_bpf[t];
    if (t < 16) glb_s[t] = g_glb[t];
    __syncthreads();

    int base = blockIdx.x * 1024;
    int rw[4];
    float px[4], py[4], pz[4];
#pragma unroll
    for (int q = 0; q < 4; q++) {
        int row = base + t + q * 256;
        int r = -1;
        float x = 0, y = 0, z = 0;
        if (row < NSROWS) {
            r = ridx[row];
            if (r >= 0) {
                int n = row >> 4;
                x = coord[r * 3 + 0] - coord[n * 3 + 0];
                y = coord[r * 3 + 1] - coord[n * 3 + 1];
                z = coord[r * 3 + 2] - coord[n * 3 + 2];
            }
        }
        rw[q] = r; px[q] = x; py[q] = y; pz[q] = z;
    }

    float acc[4][16];
#pragma unroll
    for (int q = 0; q < 4; q++)
#pragma unroll
        for (int g = 0; g < 16; g++) acc[q][g] = 0.f;

    for (int k = 0; k < 256; k++) {
        float4 pk = P4[k];
        float bp = Bpf[k];
        float h[4];
#pragma unroll
        for (int q = 0; q < 4; q++) {
            float pd = fmaf(pz[q], pk.z, fmaf(py[q], pk.y, px[q] * pk.x));
            h[q] = fmaxf(fmaf(pk.w, pd, bp), 0.f);
        }
        float4 b0 = *(const float4*)&Bs[k][0];
        float4 b1 = *(const float4*)&Bs[k][4];
        float4 b2 = *(const float4*)&Bs[k][8];
        float4 b3 = *(const float4*)&Bs[k][12];
#pragma unroll
        for (int q = 0; q < 4; q++) {
            acc[q][0]  = fmaf(h[q], b0.x, acc[q][0]);
            acc[q][1]  = fmaf(h[q], b0.y, acc[q][1]);
            acc[q][2]  = fmaf(h[q], b0.z, acc[q][2]);
            acc[q][3]  = fmaf(h[q], b0.w, acc[q][3]);
            acc[q][4]  = fmaf(h[q], b1.x, acc[q][4]);
            acc[q][5]  = fmaf(h[q], b1.y, acc[q][5]);
            acc[q][6]  = fmaf(h[q], b1.z, acc[q][6]);
            acc[q][7]  = fmaf(h[q], b1.w, acc[q][7]);
            acc[q][8]  = fmaf(h[q], b2.x, acc[q][8]);
            acc[q][9]  = fmaf(h[q], b2.y, acc[q][9]);
            acc[q][10] = fmaf(h[q], b2.z, acc[q][10]);
            acc[q][11] = fmaf(h[q], b2.w, acc[q][11]);
            acc[q][12] = fmaf(h[q], b3.x, acc[q][12]);
            acc[q][13] = fmaf(h[q], b3.y, acc[q][13]);
            acc[q][14] = fmaf(h[q], b3.z, acc[q][14]);
            acc[q][15] = fmaf(h[q], b3.w, acc[q][15]);
        }
    }

#pragma unroll
    for (int q = 0; q < 4; q++) {
        int row = base + t + q * 256;
        if (row < NSROWS) {
            int n = row >> 4;
            int r = rw[q];
#pragma unroll
            for (int g = 0; g < 16; g++) {
                float kgv = (r >= 0) ? g_kg[(size_t)r * GG + g] : 0.f;
                g_wpre[(size_t)row * GG + g] =
                    kgv - g_qg[(size_t)n * GG + g] + acc[q][g] + glb_s[g];
            }
        }
    }
}

// ---------------- K7: group stats of w_pre ----------------
__global__ void k_wstats() {
    __shared__ float ssum[16], ssq[16];
    int t = threadIdx.x;
    if (t < 16) { ssum[t] = 0.f; ssq[t] = 0.f; }
    __syncthreads();
    int g = t & 15;
    float s1 = 0, s2 = 0;
    for (int row = blockIdx.x * 16 + (t >> 4); row < NSROWS; row += gridDim.x * 16) {
        float x = g_wpre[(size_t)row * GG + g];
        s1 += x; s2 = fmaf(x, x, s2);
    }
    atomicAdd(&ssum[g], s1);
    atomicAdd(&ssq[g], s2);
    __syncthreads();
    if (t < 16) {
        atomicAdd(&g_ds[1040 + t], (double)ssum[t]);
        atomicAdd(&g_ds[1056 + t], (double)ssq[t]);
    }
}

// ---------------- K8: fold group BN ----------------
__global__ void k_final2(const float* __restrict__ g_gl, const float* __restrict__ beta_gl) {
    int g = threadIdx.x;
    if (g < 16) {
        double invNS = 1.0 / (double)NSROWS;
        double mu  = g_ds[1040 + g] * invNS;
        double var = g_ds[1056 + g] * invNS - mu * mu;
        float a = (float)((double)g_gl[g] / sqrt(var + 1e-5));
        g_aw[g] = a; g_bw[g] = beta_gl[g] - (float)mu * a;
    }
}

// ---------------- K9: fused per-point: logits -> softmax -> gathered V + Hw ----------------
__global__ void __launch_bounds__(256) k_pointG(
    const float* __restrict__ coord, const int* __restrict__ ridx,
    const float* __restrict__ Wp1,  const float* __restrict__ bp2,
    const float* __restrict__ Wwe,  const float* __restrict__ bwe,
    float* __restrict__ out)
{
    __shared__ float rl[16][17];
    __shared__ float lg[16][17];
    __shared__ float wsm[16][17];
    __shared__ float wsum[16];
    __shared__ float Wwe_s[16][16];
    __shared__ float bwe_s[16];
    __shared__ float psx[16], psy[16], psz[16];
    __shared__ int   rs[16];

    int n = blockIdx.x, t = threadIdx.x;
    Wwe_s[t >> 4][t & 15] = Wwe[t];
    if (t < 16) {
        bwe_s[t] = bwe[t];
        int r = ridx[n * SS + t];
        rs[t] = r;
        float x = 0, y = 0, z = 0;
        if (r >= 0) {
            x = coord[r * 3 + 0] - coord[n * 3 + 0];
            y = coord[r * 3 + 1] - coord[n * 3 + 1];
            z = coord[r * 3 + 2] - coord[n * 3 + 2];
        }
        psx[t] = x; psy[t] = y; psz[t] = z;
    }
    int s = t >> 4, g = t & 15;
    {
        float x = g_wpre[(size_t)n * 256 + t];
        rl[s][g] = fmaxf(fmaf(g_aw[g], x, g_bw[g]), 0.f);
    }
    __syncthreads();
    {
        float acc = bwe_s[g];
#pragma unroll
        for (int gp2 = 0; gp2 < 16; gp2++)
            acc = fmaf(rl[s][gp2], Wwe_s[gp2][g], acc);
        lg[s][g] = acc;
    }
    __syncthreads();
    if (t < 16) {
        float m = -1e30f;
#pragma unroll
        for (int ss2 = 0; ss2 < 16; ss2++) m = fmaxf(m, lg[ss2][t]);
        float sum = 0;
        float e[16];
#pragma unroll
        for (int ss2 = 0; ss2 < 16; ss2++) { e[ss2] = expf(lg[ss2][t] - m); sum += e[ss2]; }
        float inv = 1.f / sum;
        float ws = 0;
#pragma unroll
        for (int ss2 = 0; ss2 < 16; ss2++) {
            float w = (rs[ss2] >= 0) ? e[ss2] * inv : 0.f;
            wsm[ss2][t] = w; ws += w;
        }
        wsum[t] = ws;
    }
    __syncthreads();

    int c = t, gc = c >> 4;
    float hw[16];
#pragma unroll
    for (int gg = 0; gg < 16; gg++) hw[gg] = 0.f;
    float out1 = wsum[gc] * bp2[c];
    float w1c = Wp1[c], w2c = Wp1[256 + c], w3c = Wp1[512 + c];
    float apc = g_ap[c], bpc = g_bpf[c];
#pragma unroll
    for (int ss2 = 0; ss2 < 16; ss2++) {
        int r = rs[ss2];
        if (r >= 0) {
            out1 = fmaf(wsm[ss2][gc], g_V[(size_t)r * CC + c], out1);
            float pd = fmaf(psz[ss2], w3c, fmaf(psy[ss2], w2c, psx[ss2] * w1c));
            float h = fmaxf(fmaf(apc, pd, bpc), 0.f);
#pragma unroll
            for (int gg = 0; gg < 16; gg++)
                hw[gg] = fmaf(wsm[ss2][gg], h, hw[gg]);
        }
    }
    out[(size_t)n * CC + c] = out1;
#pragma unroll
    for (int gg = 0; gg < 16; gg++)
        g_Hw[(size_t)n * 4096 + gg * 256 + c] = hw[gg];
}

// ---------------- K10: projection GEMM, 2x4 micro-kernel, float4 B ----------------
__global__ void __launch_bounds__(256) k_projH(
    const float* __restrict__ Wp2, float* __restrict__ out)
{
    __shared__ __align__(16) float Bs[256][20];
    __shared__ __align__(16) float As[128][36];
    int g = blockIdx.y;
    int n0 = blockIdx.x * 128;
    int t = threadIdx.x;
    for (int l = t; l < 4096; l += 256)
        Bs[l >> 4][l & 15] = Wp2[(size_t)(l >> 4) * CC + g * 16 + (l & 15)];

    int j0 = (t & 3) * 4;
    int rp = t >> 2;          // rows rp and rp+64
    float a00 = 0, a01 = 0, a02 = 0, a03 = 0;
    float a10 = 0, a11 = 0, a12 = 0, a13 = 0;

    for (int kc = 0; kc < 8; kc++) {
        int k0 = kc * 32;
        __syncthreads();
#pragma unroll
        for (int l = t; l < 1024; l += 256) {
            int row = l >> 3, c4 = (l & 7) * 4;
            int nn = n0 + row;
            float4 v = (nn < NPTS)
                ? *(const float4*)(g_Hw + (size_t)nn * 4096 + g * 256 + k0 + c4)
                : make_float4(0.f, 0.f, 0.f, 0.f);
            *(float4*)&As[row][c4] = v;
        }
        __syncthreads();
#pragma unroll
        for (int kk = 0; kk < 32; kk++) {
            float4 b = *(const float4*)&Bs[k0 + kk][j0];
            float a0 = As[rp][kk];
            float a1 = As[rp + 64][kk];
            a00 = fmaf(a0, b.x, a00); a01 = fmaf(a0, b.y, a01);
            a02 = fmaf(a0, b.z, a02); a03 = fmaf(a0, b.w, a03);
            a10 = fmaf(a1, b.x, a10); a11 = fmaf(a1, b.y, a11);
            a12 = fmaf(a1, b.z, a12); a13 = fmaf(a1, b.w, a13);
        }
    }
    {
        int nn = n0 + rp;
        if (nn < NPTS) {
            float4* p = (float4*)(out + (size_t)nn * CC + g * 16 + j0);
            float4 cur = *p;
            cur.x += a00; cur.y += a01; cur.z += a02; cur.w += a03;
            *p = cur;
        }
    }
    {
        int nn = n0 + rp + 64;
        if (nn < NPTS) {
            float4* p = (float4*)(out + (size_t)nn * CC + g * 16 + j0);
            float4 cur = *p;
            cur.x += a10; cur.y += a11; cur.z += a12; cur.w += a13;
            *p = cur;
        }
    }
}

// ---------------- launch ----------------
extern "C" void kernel_launch(void* const* d_in, const int* in_sizes, int n_in,
                              void* d_out, int out_size) {
    const float* feat   = (const float*)d_in[0];
    const float* coord  = (const float*)d_in[1];
    const int*   ridx   = (const int*)  d_in[2];
    const float* Wq     = (const float*)d_in[3];
    const float* bq     = (const float*)d_in[4];
    const float* gq     = (const float*)d_in[5];
    const float* betaq  = (const float*)d_in[6];
    const float* Wk     = (const float*)d_in[7];
    const float* bk     = (const float*)d_in[8];
    const float* gk     = (const float*)d_in[9];
    const float* betak  = (const float*)d_in[10];
    const float* Wv     = (const float*)d_in[11];
    const float* bv     = (const float*)d_in[12];
    const float* Wp1    = (const float*)d_in[13];
    const float* bp1    = (const float*)d_in[14];
    const float* gp     = (const float*)d_in[15];
    const float* betap  = (const float*)d_in[16];
    const float* Wp2    = (const float*)d_in[17];
    const float* bp2    = (const float*)d_in[18];
    const float* w_gl   = (const float*)d_in[19];
    const float* g_gl   = (const float*)d_in[20];
    const float* betagl = (const float*)d_in[21];
    const float* Wwe    = (const float*)d_in[22];
    const float* bwe    = (const float*)d_in[23];
    float* out = (float*)d_out;

    cudaFuncSetAttribute(k_gemm_tc, cudaFuncAttributeMaxDynamicSharedMemorySize, GEMM_SMEM);

    k_zero<<<5, 256>>>();
    k_cvt_feat<<<25000, 256>>>(feat);
    k_cvt_W<<<192, 256>>>(Wq, Wk, Wv);
    dim3 gtc((NPTS + 127) / 128, 6);
    k_gemm_tc<<<gtc, 256, GEMM_SMEM>>>(bq, bk, bv);
    k_posmom<<<NSROWS / 256, 256>>>(coord, ridx);
    k_final1<<<1, 256>>>(gq, betaq, gk, betak, Wp1, bp1, gp, betap, Wp2, bp2, w_gl);
    k_qkgroup<<<NPTS / 8, 256>>>(w_gl);
    k_wpre<<<(NSROWS + 1023) / 1024, 256>>>(coord, ridx, Wp1);
    k_wstats<<<512, 256>>>();
    k_final2<<<1, 32>>>(g_gl, betagl);
    k_pointG<<<NPTS, 256>>>(coord, ridx, Wp1, bp2, Wwe, bwe, out);
    dim3 gg2((NPTS + 127) / 128, 16);
    k_projH<<<gg2, 256>>>(Wp2, out);
}